// round 1
// baseline (speedup 1.0000x reference)
#include <cuda_runtime.h>
#include <cuda_bf16.h>

// Problem constants
#define Bn   4
#define Sn   2048
#define HIDn 2048
#define Hn   16
#define Dn   128
#define Mn   8192  // B*S

// Scratch (allocation-free rule: __device__ globals)
__device__ float g_q[(size_t)Bn * Hn * Sn * Dn];    // [B,H,S,D]
__device__ float g_ctx[(size_t)Bn * Sn * Hn * Dn];  // [B,S,H*D]

// ---------------------------------------------------------------------------
// Shared NT-GEMM core: C[128x128] tile of A[M,K] * W[N,K]^T, K=2048, BK=16
// 256 threads, 8x8 micro-tile per thread. A/W tiles transposed into smem.
// ---------------------------------------------------------------------------
__device__ __forceinline__ void gemm128_core(const float* __restrict__ A,
                                             const float* __restrict__ W,
                                             float (*As)[132], float (*Bs)[132],
                                             int m0, int n0, float acc[8][8])
{
    const int tid = threadIdx.x;
    const int tx = tid & 15;
    const int ty = tid >> 4;

    for (int k0 = 0; k0 < HIDn; k0 += 16) {
        #pragma unroll
        for (int i = 0; i < 2; i++) {
            int idx = tid + i * 256;          // 0..511
            int row = idx >> 2;               // 0..127
            int k4  = (idx & 3) * 4;          // 0,4,8,12
            float4 va = *reinterpret_cast<const float4*>(A + (size_t)(m0 + row) * HIDn + k0 + k4);
            As[k4 + 0][row] = va.x; As[k4 + 1][row] = va.y;
            As[k4 + 2][row] = va.z; As[k4 + 3][row] = va.w;
            float4 vb = *reinterpret_cast<const float4*>(W + (size_t)(n0 + row) * HIDn + k0 + k4);
            Bs[k4 + 0][row] = vb.x; Bs[k4 + 1][row] = vb.y;
            Bs[k4 + 2][row] = vb.z; Bs[k4 + 3][row] = vb.w;
        }
        __syncthreads();

        #pragma unroll
        for (int kk = 0; kk < 16; kk++) {
            float a[8], b[8];
            *reinterpret_cast<float4*>(&a[0]) = *reinterpret_cast<const float4*>(&As[kk][ty * 8]);
            *reinterpret_cast<float4*>(&a[4]) = *reinterpret_cast<const float4*>(&As[kk][ty * 8 + 4]);
            *reinterpret_cast<float4*>(&b[0]) = *reinterpret_cast<const float4*>(&Bs[kk][tx * 8]);
            *reinterpret_cast<float4*>(&b[4]) = *reinterpret_cast<const float4*>(&Bs[kk][tx * 8 + 4]);
            #pragma unroll
            for (int r = 0; r < 8; r++)
                #pragma unroll
                for (int c = 0; c < 8; c++)
                    acc[r][c] = fmaf(a[r], b[c], acc[r][c]);
        }
        __syncthreads();
    }
}

// ---------------------------------------------------------------------------
// QKV projection: z=0 -> Q into g_q [B,H,S,D]; z=1 -> K into kv cache slot 0;
// z=2 -> V into kv cache slot 1. kv layout: [B,H,2,S,D].
// ---------------------------------------------------------------------------
__global__ void __launch_bounds__(256) proj_gemm(const float* __restrict__ x,
                                                 const float* __restrict__ Wq,
                                                 const float* __restrict__ Wk,
                                                 const float* __restrict__ Wv,
                                                 float* __restrict__ qout,
                                                 float* __restrict__ kvout)
{
    __shared__ __align__(16) float As[16][132];
    __shared__ __align__(16) float Bs[16][132];

    const int z = blockIdx.z;
    const float* W = (z == 0) ? Wq : (z == 1) ? Wk : Wv;
    const int m0 = blockIdx.y * 128;
    const int n0 = blockIdx.x * 128;

    float acc[8][8] = {};
    gemm128_core(x, W, As, Bs, m0, n0, acc);

    const int tid = threadIdx.x;
    const int tx = tid & 15;
    const int ty = tid >> 4;
    float* dst = (z == 0) ? qout : kvout;

    #pragma unroll
    for (int r = 0; r < 8; r++) {
        int m = m0 + ty * 8 + r;
        int b = m >> 11;          // /Sn
        int s = m & (Sn - 1);
        #pragma unroll
        for (int cg = 0; cg < 2; cg++) {
            int n = n0 + tx * 8 + cg * 4;
            int h = n >> 7;       // /Dn
            int d = n & (Dn - 1);
            size_t idx;
            if (z == 0)
                idx = (((size_t)(b * Hn + h)) * Sn + s) * Dn + d;
            else
                idx = ((((size_t)(b * Hn + h)) * 2 + (z - 1)) * Sn + s) * Dn + d;
            *reinterpret_cast<float4*>(dst + idx) = *reinterpret_cast<float4*>(&acc[r][cg * 4]);
        }
    }
}

// ---------------------------------------------------------------------------
// Output projection: out[M, HID] = ctx[M, H*D] * Wo[HID, H*D]^T
// ---------------------------------------------------------------------------
__global__ void __launch_bounds__(256) out_gemm(const float* __restrict__ A,
                                                const float* __restrict__ W,
                                                float* __restrict__ out)
{
    __shared__ __align__(16) float As[16][132];
    __shared__ __align__(16) float Bs[16][132];

    const int m0 = blockIdx.y * 128;
    const int n0 = blockIdx.x * 128;

    float acc[8][8] = {};
    gemm128_core(A, W, As, Bs, m0, n0, acc);

    const int tid = threadIdx.x;
    const int tx = tid & 15;
    const int ty = tid >> 4;

    #pragma unroll
    for (int r = 0; r < 8; r++) {
        size_t rowoff = (size_t)(m0 + ty * 8 + r) * HIDn + n0 + tx * 8;
        *reinterpret_cast<float4*>(out + rowoff)     = *reinterpret_cast<float4*>(&acc[r][0]);
        *reinterpret_cast<float4*>(out + rowoff + 4) = *reinterpret_cast<float4*>(&acc[r][4]);
    }
}

// ---------------------------------------------------------------------------
// Causal flash attention, fp32.
// Grid: (S/64, B*H). 256 threads. 64 q-rows per CTA, 64-key tiles.
// Thread (ty,tx), ty=tid/16, tx=tid%16:
//   scores: owns rows ty*4..+3, cols tx*4..+3 of 64x64
//   acc/PV: owns rows ty*4..+3, cols tx*8..+7 of 64x128
// smem: Qs_t[128][68], Ks_t[128][68] (d-major, broadcast-friendly),
//       Vs[64][128] (row-major), Ps[64][68] (qrow-major).
// ---------------------------------------------------------------------------
#define ATT_SMEM_FLOATS (128*68 + 128*68 + 64*128 + 64*68)

__global__ void __launch_bounds__(256, 1) attn_kernel(const float* __restrict__ q,
                                                      const float* __restrict__ kv,
                                                      float* __restrict__ ctx)
{
    extern __shared__ __align__(16) float sm[];
    float* Qs = sm;                     // [128][68]
    float* Ks = Qs + 128 * 68;          // [128][68]
    float* Vs = Ks + 128 * 68;          // [64][128]
    float* Ps = Vs + 64 * 128;          // [64][68]

    const int q0 = blockIdx.x * 64;
    const int bh = blockIdx.y;
    const float* qb = q  + (size_t)bh * Sn * Dn;
    const float* kb = kv + (size_t)bh * 2 * Sn * Dn;
    const float* vb = kb + (size_t)Sn * Dn;

    const int tid = threadIdx.x;
    const int tx = tid & 15;
    const int ty = tid >> 4;

    // Load Q tile transposed: Qs[d][s]
    #pragma unroll
    for (int i = 0; i < 8; i++) {
        int idx = tid + i * 256;        // 0..2047
        int s  = idx >> 5;              // 0..63
        int d4 = (idx & 31) * 4;        // 0..124
        float4 v = *reinterpret_cast<const float4*>(qb + (size_t)(q0 + s) * Dn + d4);
        Qs[(d4 + 0) * 68 + s] = v.x;
        Qs[(d4 + 1) * 68 + s] = v.y;
        Qs[(d4 + 2) * 68 + s] = v.z;
        Qs[(d4 + 3) * 68 + s] = v.w;
    }

    float acc[4][8] = {};
    float m_i[4], l_i[4];
    #pragma unroll
    for (int r = 0; r < 4; r++) { m_i[r] = -1e30f; l_i[r] = 0.0f; }

    const int nkt = (q0 >> 6) + 1;
    const float scale = 0.08838834764831845f;  // 1/sqrt(128)

    for (int jt = 0; jt < nkt; jt++) {
        const int j0 = jt * 64;
        __syncthreads();  // prior reads of Ks/Vs/Ps done before overwrite

        // Load K tile transposed + V tile direct
        #pragma unroll
        for (int i = 0; i < 8; i++) {
            int idx = tid + i * 256;
            int s  = idx >> 5;
            int d4 = (idx & 31) * 4;
            float4 v = *reinterpret_cast<const float4*>(kb + (size_t)(j0 + s) * Dn + d4);
            Ks[(d4 + 0) * 68 + s] = v.x;
            Ks[(d4 + 1) * 68 + s] = v.y;
            Ks[(d4 + 2) * 68 + s] = v.z;
            Ks[(d4 + 3) * 68 + s] = v.w;
            float4 w = *reinterpret_cast<const float4*>(vb + (size_t)(j0 + s) * Dn + d4);
            *reinterpret_cast<float4*>(&Vs[s * 128 + d4]) = w;
        }
        __syncthreads();

        // scores = Q K^T
        float sc[4][4] = {};
        #pragma unroll 4
        for (int kk = 0; kk < 128; kk++) {
            float4 a4 = *reinterpret_cast<const float4*>(&Qs[kk * 68 + ty * 4]);
            float4 b4 = *reinterpret_cast<const float4*>(&Ks[kk * 68 + tx * 4]);
            float av[4] = {a4.x, a4.y, a4.z, a4.w};
            float bv[4] = {b4.x, b4.y, b4.z, b4.w};
            #pragma unroll
            for (int r = 0; r < 4; r++)
                #pragma unroll
                for (int c = 0; c < 4; c++)
                    sc[r][c] = fmaf(av[r], bv[c], sc[r][c]);
        }

        // scale + causal mask + row max
        float rmax[4];
        #pragma unroll
        for (int r = 0; r < 4; r++) {
            int qg = q0 + ty * 4 + r;
            rmax[r] = -1e30f;
            #pragma unroll
            for (int c = 0; c < 4; c++) {
                int kg = j0 + tx * 4 + c;
                sc[r][c] = (kg <= qg) ? sc[r][c] * scale : -1e30f;
                rmax[r] = fmaxf(rmax[r], sc[r][c]);
            }
        }
        #pragma unroll
        for (int off = 8; off > 0; off >>= 1)
            #pragma unroll
            for (int r = 0; r < 4; r++)
                rmax[r] = fmaxf(rmax[r], __shfl_xor_sync(0xffffffffu, rmax[r], off));

        // online softmax update
        float p[4][4], rsum[4];
        #pragma unroll
        for (int r = 0; r < 4; r++) {
            float nm = fmaxf(m_i[r], rmax[r]);
            float alpha = __expf(m_i[r] - nm);
            m_i[r] = nm;
            rsum[r] = 0.0f;
            #pragma unroll
            for (int c = 0; c < 4; c++) {
                p[r][c] = __expf(sc[r][c] - nm);
                rsum[r] += p[r][c];
            }
            l_i[r] *= alpha;
            #pragma unroll
            for (int c = 0; c < 8; c++) acc[r][c] *= alpha;
        }
        #pragma unroll
        for (int off = 8; off > 0; off >>= 1)
            #pragma unroll
            for (int r = 0; r < 4; r++)
                rsum[r] += __shfl_xor_sync(0xffffffffu, rsum[r], off);
        #pragma unroll
        for (int r = 0; r < 4; r++) l_i[r] += rsum[r];

        // stage P: Ps[qrow][key]
        #pragma unroll
        for (int r = 0; r < 4; r++)
            *reinterpret_cast<float4*>(&Ps[(ty * 4 + r) * 68 + tx * 4]) =
                *reinterpret_cast<float4*>(&p[r][0]);
        __syncthreads();

        // acc += P V
        #pragma unroll 2
        for (int kk = 0; kk < 64; kk++) {
            float pr[4];
            #pragma unroll
            for (int r = 0; r < 4; r++) pr[r] = Ps[(ty * 4 + r) * 68 + kk];
            float4 v0 = *reinterpret_cast<const float4*>(&Vs[kk * 128 + tx * 8]);
            float4 v1 = *reinterpret_cast<const float4*>(&Vs[kk * 128 + tx * 8 + 4]);
            #pragma unroll
            for (int r = 0; r < 4; r++) {
                acc[r][0] = fmaf(pr[r], v0.x, acc[r][0]);
                acc[r][1] = fmaf(pr[r], v0.y, acc[r][1]);
                acc[r][2] = fmaf(pr[r], v0.z, acc[r][2]);
                acc[r][3] = fmaf(pr[r], v0.w, acc[r][3]);
                acc[r][4] = fmaf(pr[r], v1.x, acc[r][4]);
                acc[r][5] = fmaf(pr[r], v1.y, acc[r][5]);
                acc[r][6] = fmaf(pr[r], v1.z, acc[r][6]);
                acc[r][7] = fmaf(pr[r], v1.w, acc[r][7]);
            }
        }
    }

    // write ctx[b][s][h*D + d]
    const int b = bh >> 4;
    const int h = bh & 15;
    #pragma unroll
    for (int r = 0; r < 4; r++) {
        float inv = 1.0f / l_i[r];
        float4 o0, o1;
        o0.x = acc[r][0] * inv; o0.y = acc[r][1] * inv;
        o0.z = acc[r][2] * inv; o0.w = acc[r][3] * inv;
        o1.x = acc[r][4] * inv; o1.y = acc[r][5] * inv;
        o1.z = acc[r][6] * inv; o1.w = acc[r][7] * inv;
        size_t base = ((size_t)b * Sn + q0 + ty * 4 + r) * (Hn * Dn) + h * Dn + tx * 8;
        *reinterpret_cast<float4*>(ctx + base)     = o0;
        *reinterpret_cast<float4*>(ctx + base + 4) = o1;
    }
}

// ---------------------------------------------------------------------------
// Launch
// ---------------------------------------------------------------------------
extern "C" void kernel_launch(void* const* d_in, const int* in_sizes, int n_in,
                              void* d_out, int out_size)
{
    const float* x  = (const float*)d_in[0];
    const float* Wq = (const float*)d_in[1];
    const float* Wk = (const float*)d_in[2];
    const float* Wv = (const float*)d_in[3];
    const float* Wo = (const float*)d_in[4];

    float* out = (float*)d_out;                               // [B,S,HID]
    float* kv  = out + (size_t)Bn * Sn * HIDn;                // [B,H,2,S,D]

    float* qs;  cudaGetSymbolAddress((void**)&qs,  g_q);
    float* ctx; cudaGetSymbolAddress((void**)&ctx, g_ctx);

    // 1) Q/K/V projections (K,V written straight into the kv-cache output)
    dim3 gproj(HIDn / 128, Mn / 128, 3);
    proj_gemm<<<gproj, 256>>>(x, Wq, Wk, Wv, qs, kv);

    // 2) causal flash attention
    size_t attn_smem = (size_t)ATT_SMEM_FLOATS * sizeof(float);
    cudaFuncSetAttribute(attn_kernel, cudaFuncAttributeMaxDynamicSharedMemorySize,
                         (int)attn_smem);
    dim3 gattn(Sn / 64, Bn * Hn);
    attn_kernel<<<gattn, 256, attn_smem>>>(qs, kv, ctx);

    // 3) output projection
    dim3 gout(HIDn / 128, Mn / 128);
    out_gemm<<<gout, 256>>>(ctx, Wo, out);
}

// round 3
// speedup vs baseline: 1.9025x; 1.9025x over previous
#include <cuda_runtime.h>
#include <cuda_bf16.h>
#include <cstdint>

// Problem constants
#define Bn   4
#define Sn   2048
#define HIDn 2048
#define Hn   16
#define Dn   128
#define Mn   8192  // B*S

// Scratch (allocation-free rule: __device__ globals)
__device__ float g_q  [(size_t)Bn * Hn * Sn * Dn];   // [B,H,S,D]
__device__ float g_ctx[(size_t)Mn * HIDn];           // [B,S,H*D] tf32-rounded
__device__ float g_xr [(size_t)Mn * HIDn];           // x rounded to tf32
__device__ float g_wr [4][(size_t)HIDn * HIDn];      // Wq,Wk,Wv,Wo rounded to tf32

// ---------------------------------------------------------------------------
// helpers
// ---------------------------------------------------------------------------
__device__ __forceinline__ uint32_t smem_u32(const void* p) {
    uint32_t a;
    asm("{ .reg .u64 t; cvta.to.shared.u64 t, %1; cvt.u32.u64 %0, t; }"
        : "=r"(a) : "l"(p));
    return a;
}
__device__ __forceinline__ float tf32r(float x) {
    float y;
    asm("cvt.rn.tf32.f32 %0, %1;" : "=f"(y) : "f"(x));
    return y;
}
__device__ __forceinline__ void cpasync16(uint32_t saddr, const void* g) {
    asm volatile("cp.async.cg.shared.global [%0], [%1], 16;" :: "r"(saddr), "l"(g));
}
__device__ __forceinline__ void mma_tf32(float c[4], const uint32_t a[4], const uint32_t b[2]) {
    asm volatile("mma.sync.aligned.m16n8k8.row.col.f32.tf32.tf32.f32 "
                 "{%0,%1,%2,%3}, {%4,%5,%6,%7}, {%8,%9}, {%0,%1,%2,%3};"
                 : "+f"(c[0]), "+f"(c[1]), "+f"(c[2]), "+f"(c[3])
                 : "r"(a[0]), "r"(a[1]), "r"(a[2]), "r"(a[3]), "r"(b[0]), "r"(b[1]));
}

// ---------------------------------------------------------------------------
// tf32 rounding prepass (RN, unbiased)
// ---------------------------------------------------------------------------
__global__ void __launch_bounds__(256) round_tf32(const float4* __restrict__ in,
                                                  float4* __restrict__ out, int n4) {
    int i = blockIdx.x * blockDim.x + threadIdx.x;
    if (i < n4) {
        float4 v = in[i];
        v.x = tf32r(v.x); v.y = tf32r(v.y); v.z = tf32r(v.z); v.w = tf32r(v.w);
        out[i] = v;
    }
}

// ---------------------------------------------------------------------------
// tf32 mma.sync NT-GEMM: C[128x128] tile of A[M,2048] * W[N,2048]^T
// 256 threads = 8 warps (2m x 4n), warp tile 64x32, BK=32, double-buffered
// cp.async. Fragments via ldmatrix.b16 (8x8 b16 == 8x4 fp32 tile).
// MODE 0: QKV projection (blockIdx.z selects W; scatter epilogue)
// MODE 1: output projection (row-major epilogue)
// ---------------------------------------------------------------------------
#define LDW 36                       // row stride in floats (bank-spread, 16B-aligned)
#define TILE_F (128 * LDW)           // one operand tile
#define STAGE_F (2 * TILE_F)         // A + B per stage
#define GEMM_SMEM (2 * STAGE_F * 4)  // 2 stages, bytes (= 73728)

template<int MODE>
__global__ void __launch_bounds__(256, 2) gemm_mma(const float* __restrict__ A_,
                                                   const float* __restrict__ W0,
                                                   const float* __restrict__ W1,
                                                   const float* __restrict__ W2,
                                                   float* __restrict__ qout,
                                                   float* __restrict__ kvout)
{
    extern __shared__ float sm[];

    const int tid  = threadIdx.x;
    const int wid  = tid >> 5;
    const int lane = tid & 31;
    const int wm = (wid >> 2) * 64;   // warp m offset in CTA tile
    const int wn = (wid & 3) * 32;    // warp n offset

    const int m0 = blockIdx.y * 128;
    const int n0 = blockIdx.x * 128;
    int z = 0;
    const float* W = W0;
    if (MODE == 0) { z = blockIdx.z; W = (z == 0) ? W0 : (z == 1) ? W1 : W2; }

    // ldmatrix source row/col within fragment, per lane
    const int amat = lane >> 3, arow = lane & 7;
    const int a_r = (amat & 1) * 8 + arow;      // row within 16-row frag
    const int a_c = (amat >> 1) * 4;            // fp32 col offset within k8
    const int b_r = lane & 7;                   // n within 8-col frag
    const int b_c = ((lane >> 3) & 1) * 4;      // fp32 col offset within k8

    float acc[4][4][4] = {};                    // [mtile][ntile][c0..c3]

    auto load_stage = [&](int j, int st) {
        float* As = sm + st * STAGE_F;
        float* Bs = As + TILE_F;
        const int k0 = j * 32;
        #pragma unroll
        for (int i = 0; i < 4; i++) {
            int idx = tid + i * 256;            // 0..1023
            int row = idx >> 3;                 // 0..127
            int c   = idx & 7;                  // 16B chunk (4 floats)
            cpasync16(smem_u32(As + row * LDW + c * 4),
                      A_ + (size_t)(m0 + row) * HIDn + k0 + c * 4);
            cpasync16(smem_u32(Bs + row * LDW + c * 4),
                      W  + (size_t)(n0 + row) * HIDn + k0 + c * 4);
        }
        asm volatile("cp.async.commit_group;");
    };

    const int nk = HIDn / 32;                   // 64
    load_stage(0, 0);

    for (int j = 0; j < nk; j++) {
        if (j + 1 < nk) {
            load_stage(j + 1, (j + 1) & 1);
            asm volatile("cp.async.wait_group 1;" ::: "memory");
        } else {
            asm volatile("cp.async.wait_group 0;" ::: "memory");
        }
        __syncthreads();

        const float* As = sm + (j & 1) * STAGE_F;
        const float* Bs = As + TILE_F;

        #pragma unroll
        for (int ks = 0; ks < 4; ks++) {
            const int k0 = ks * 8;
            uint32_t a[4][4];
            #pragma unroll
            for (int i = 0; i < 4; i++) {
                uint32_t ad = smem_u32(As + (wm + i * 16 + a_r) * LDW + k0 + a_c);
                asm volatile("ldmatrix.sync.aligned.m8n8.x4.shared.b16 {%0,%1,%2,%3}, [%4];"
                             : "=r"(a[i][0]), "=r"(a[i][1]), "=r"(a[i][2]), "=r"(a[i][3])
                             : "r"(ad));
            }
            uint32_t b[4][2];
            #pragma unroll
            for (int t = 0; t < 4; t++) {
                uint32_t bd = smem_u32(Bs + (wn + t * 8 + b_r) * LDW + k0 + b_c);
                asm volatile("ldmatrix.sync.aligned.m8n8.x2.shared.b16 {%0,%1}, [%2];"
                             : "=r"(b[t][0]), "=r"(b[t][1]) : "r"(bd));
            }
            #pragma unroll
            for (int i = 0; i < 4; i++)
                #pragma unroll
                for (int t = 0; t < 4; t++)
                    mma_tf32(acc[i][t], a[i], b[t]);
        }
        __syncthreads();
    }

    // Epilogue. Thread owns rows (wm+i*16 + lane/4, +8), cols (wn+t*8 + 2*(lane&3), +1)
    const int er = lane >> 2;
    const int ec = (lane & 3) * 2;

    #pragma unroll
    for (int i = 0; i < 4; i++) {
        const int r0 = m0 + wm + i * 16 + er;
        #pragma unroll
        for (int half = 0; half < 2; half++) {
            const int m = r0 + half * 8;
            if (MODE == 1) {
                size_t o = (size_t)m * HIDn + n0 + wn + ec;
                #pragma unroll
                for (int t = 0; t < 4; t++) {
                    float2 v = make_float2(acc[i][t][half * 2], acc[i][t][half * 2 + 1]);
                    *reinterpret_cast<float2*>(qout + o + t * 8) = v;
                }
            } else {
                const int b = m >> 11;
                const int s = m & (Sn - 1);
                const int h = n0 >> 7;          // N tile == one head (D=128)
                float* dst;
                size_t bi;
                if (z == 0) { dst = qout;  bi = (((size_t)(b * Hn + h)) * Sn + s) * Dn; }
                else        { dst = kvout; bi = ((((size_t)(b * Hn + h)) * 2 + (z - 1)) * Sn + s) * Dn; }
                bi += wn + ec;
                #pragma unroll
                for (int t = 0; t < 4; t++) {
                    float2 v = make_float2(acc[i][t][half * 2], acc[i][t][half * 2 + 1]);
                    *reinterpret_cast<float2*>(dst + bi + t * 8) = v;
                }
            }
        }
    }
}

// ---------------------------------------------------------------------------
// Causal flash attention, fp32 SIMT (R1-proven; ctx stored tf32-rounded)
// ---------------------------------------------------------------------------
#define ATT_SMEM_FLOATS (128*68 + 128*68 + 64*128 + 64*68)

__global__ void __launch_bounds__(256, 1) attn_kernel(const float* __restrict__ q,
                                                      const float* __restrict__ kv,
                                                      float* __restrict__ ctx)
{
    extern __shared__ __align__(16) float sm[];
    float* Qs = sm;                     // [128][68]
    float* Ks = Qs + 128 * 68;          // [128][68]
    float* Vs = Ks + 128 * 68;          // [64][128]
    float* Ps = Vs + 64 * 128;          // [64][68]

    const int q0 = blockIdx.x * 64;
    const int bh = blockIdx.y;
    const float* qb = q  + (size_t)bh * Sn * Dn;
    const float* kb = kv + (size_t)bh * 2 * Sn * Dn;
    const float* vb = kb + (size_t)Sn * Dn;

    const int tid = threadIdx.x;
    const int tx = tid & 15;
    const int ty = tid >> 4;

    #pragma unroll
    for (int i = 0; i < 8; i++) {
        int idx = tid + i * 256;
        int s  = idx >> 5;
        int d4 = (idx & 31) * 4;
        float4 v = *reinterpret_cast<const float4*>(qb + (size_t)(q0 + s) * Dn + d4);
        Qs[(d4 + 0) * 68 + s] = v.x;
        Qs[(d4 + 1) * 68 + s] = v.y;
        Qs[(d4 + 2) * 68 + s] = v.z;
        Qs[(d4 + 3) * 68 + s] = v.w;
    }

    float acc[4][8] = {};
    float m_i[4], l_i[4];
    #pragma unroll
    for (int r = 0; r < 4; r++) { m_i[r] = -1e30f; l_i[r] = 0.0f; }

    const int nkt = (q0 >> 6) + 1;
    const float scale = 0.08838834764831845f;

    for (int jt = 0; jt < nkt; jt++) {
        const int j0 = jt * 64;
        __syncthreads();

        #pragma unroll
        for (int i = 0; i < 8; i++) {
            int idx = tid + i * 256;
            int s  = idx >> 5;
            int d4 = (idx & 31) * 4;
            float4 v = *reinterpret_cast<const float4*>(kb + (size_t)(j0 + s) * Dn + d4);
            Ks[(d4 + 0) * 68 + s] = v.x;
            Ks[(d4 + 1) * 68 + s] = v.y;
            Ks[(d4 + 2) * 68 + s] = v.z;
            Ks[(d4 + 3) * 68 + s] = v.w;
            float4 w = *reinterpret_cast<const float4*>(vb + (size_t)(j0 + s) * Dn + d4);
            *reinterpret_cast<float4*>(&Vs[s * 128 + d4]) = w;
        }
        __syncthreads();

        float sc[4][4] = {};
        #pragma unroll 4
        for (int kk = 0; kk < 128; kk++) {
            float4 a4 = *reinterpret_cast<const float4*>(&Qs[kk * 68 + ty * 4]);
            float4 b4 = *reinterpret_cast<const float4*>(&Ks[kk * 68 + tx * 4]);
            float av[4] = {a4.x, a4.y, a4.z, a4.w};
            float bv[4] = {b4.x, b4.y, b4.z, b4.w};
            #pragma unroll
            for (int r = 0; r < 4; r++)
                #pragma unroll
                for (int c = 0; c < 4; c++)
                    sc[r][c] = fmaf(av[r], bv[c], sc[r][c]);
        }

        float rmax[4];
        #pragma unroll
        for (int r = 0; r < 4; r++) {
            int qg = q0 + ty * 4 + r;
            rmax[r] = -1e30f;
            #pragma unroll
            for (int c = 0; c < 4; c++) {
                int kg = j0 + tx * 4 + c;
                sc[r][c] = (kg <= qg) ? sc[r][c] * scale : -1e30f;
                rmax[r] = fmaxf(rmax[r], sc[r][c]);
            }
        }
        #pragma unroll
        for (int off = 8; off > 0; off >>= 1)
            #pragma unroll
            for (int r = 0; r < 4; r++)
                rmax[r] = fmaxf(rmax[r], __shfl_xor_sync(0xffffffffu, rmax[r], off));

        float p[4][4], rsum[4];
        #pragma unroll
        for (int r = 0; r < 4; r++) {
            float nm = fmaxf(m_i[r], rmax[r]);
            float alpha = __expf(m_i[r] - nm);
            m_i[r] = nm;
            rsum[r] = 0.0f;
            #pragma unroll
            for (int c = 0; c < 4; c++) {
                p[r][c] = __expf(sc[r][c] - nm);
                rsum[r] += p[r][c];
            }
            l_i[r] *= alpha;
            #pragma unroll
            for (int c = 0; c < 8; c++) acc[r][c] *= alpha;
        }
        #pragma unroll
        for (int off = 8; off > 0; off >>= 1)
            #pragma unroll
            for (int r = 0; r < 4; r++)
                rsum[r] += __shfl_xor_sync(0xffffffffu, rsum[r], off);
        #pragma unroll
        for (int r = 0; r < 4; r++) l_i[r] += rsum[r];

        #pragma unroll
        for (int r = 0; r < 4; r++)
            *reinterpret_cast<float4*>(&Ps[(ty * 4 + r) * 68 + tx * 4]) =
                *reinterpret_cast<float4*>(&p[r][0]);
        __syncthreads();

        #pragma unroll 2
        for (int kk = 0; kk < 64; kk++) {
            float pr[4];
            #pragma unroll
            for (int r = 0; r < 4; r++) pr[r] = Ps[(ty * 4 + r) * 68 + kk];
            float4 v0 = *reinterpret_cast<const float4*>(&Vs[kk * 128 + tx * 8]);
            float4 v1 = *reinterpret_cast<const float4*>(&Vs[kk * 128 + tx * 8 + 4]);
            #pragma unroll
            for (int r = 0; r < 4; r++) {
                acc[r][0] = fmaf(pr[r], v0.x, acc[r][0]);
                acc[r][1] = fmaf(pr[r], v0.y, acc[r][1]);
                acc[r][2] = fmaf(pr[r], v0.z, acc[r][2]);
                acc[r][3] = fmaf(pr[r], v0.w, acc[r][3]);
                acc[r][4] = fmaf(pr[r], v1.x, acc[r][4]);
                acc[r][5] = fmaf(pr[r], v1.y, acc[r][5]);
                acc[r][6] = fmaf(pr[r], v1.z, acc[r][6]);
                acc[r][7] = fmaf(pr[r], v1.w, acc[r][7]);
            }
        }
    }

    const int b = bh >> 4;
    const int h = bh & 15;
    #pragma unroll
    for (int r = 0; r < 4; r++) {
        float inv = 1.0f / l_i[r];
        float4 o0, o1;
        o0.x = tf32r(acc[r][0] * inv); o0.y = tf32r(acc[r][1] * inv);
        o0.z = tf32r(acc[r][2] * inv); o0.w = tf32r(acc[r][3] * inv);
        o1.x = tf32r(acc[r][4] * inv); o1.y = tf32r(acc[r][5] * inv);
        o1.z = tf32r(acc[r][6] * inv); o1.w = tf32r(acc[r][7] * inv);
        size_t base = ((size_t)b * Sn + q0 + ty * 4 + r) * (Hn * Dn) + h * Dn + tx * 8;
        *reinterpret_cast<float4*>(ctx + base)     = o0;
        *reinterpret_cast<float4*>(ctx + base + 4) = o1;
    }
}

// ---------------------------------------------------------------------------
// Launch
// ---------------------------------------------------------------------------
extern "C" void kernel_launch(void* const* d_in, const int* in_sizes, int n_in,
                              void* d_out, int out_size)
{
    const float* x  = (const float*)d_in[0];
    const float* Wq = (const float*)d_in[1];
    const float* Wk = (const float*)d_in[2];
    const float* Wv = (const float*)d_in[3];
    const float* Wo = (const float*)d_in[4];

    float* out = (float*)d_out;                    // [B,S,HID]
    float* kv  = out + (size_t)Bn * Sn * HIDn;     // [B,H,2,S,D]

    float* qs;  cudaGetSymbolAddress((void**)&qs,  g_q);
    float* ctx; cudaGetSymbolAddress((void**)&ctx, g_ctx);
    float* xr;  cudaGetSymbolAddress((void**)&xr,  g_xr);
    float* wr;  cudaGetSymbolAddress((void**)&wr,  g_wr);

    // 0) round inputs to tf32 (RN)
    {
        int n4x = Mn * HIDn / 4;
        int n4w = HIDn * HIDn / 4;
        round_tf32<<<(n4x + 255) / 256, 256>>>((const float4*)x,  (float4*)xr, n4x);
        round_tf32<<<(n4w + 255) / 256, 256>>>((const float4*)Wq, (float4*)(wr + 0 * (size_t)HIDn * HIDn), n4w);
        round_tf32<<<(n4w + 255) / 256, 256>>>((const float4*)Wk, (float4*)(wr + 1 * (size_t)HIDn * HIDn), n4w);
        round_tf32<<<(n4w + 255) / 256, 256>>>((const float4*)Wv, (float4*)(wr + 2 * (size_t)HIDn * HIDn), n4w);
        round_tf32<<<(n4w + 255) / 256, 256>>>((const float4*)Wo, (float4*)(wr + 3 * (size_t)HIDn * HIDn), n4w);
    }

    // 1) Q/K/V projections (K,V straight into kv-cache output region)
    cudaFuncSetAttribute(gemm_mma<0>, cudaFuncAttributeMaxDynamicSharedMemorySize, GEMM_SMEM);
    cudaFuncSetAttribute(gemm_mma<1>, cudaFuncAttributeMaxDynamicSharedMemorySize, GEMM_SMEM);
    dim3 gproj(HIDn / 128, Mn / 128, 3);
    gemm_mma<0><<<gproj, 256, GEMM_SMEM>>>(xr,
                                           wr + 0 * (size_t)HIDn * HIDn,
                                           wr + 1 * (size_t)HIDn * HIDn,
                                           wr + 2 * (size_t)HIDn * HIDn,
                                           qs, kv);

    // 2) causal flash attention (fp32)
    size_t attn_smem = (size_t)ATT_SMEM_FLOATS * sizeof(float);
    cudaFuncSetAttribute(attn_kernel, cudaFuncAttributeMaxDynamicSharedMemorySize,
                         (int)attn_smem);
    dim3 gattn(Sn / 64, Bn * Hn);
    attn_kernel<<<gattn, 256, attn_smem>>>(qs, kv, ctx);

    // 3) output projection
    dim3 gout(HIDn / 128, Mn / 128, 1);
    gemm_mma<1><<<gout, 256, GEMM_SMEM>>>(ctx,
                                          wr + 3 * (size_t)HIDn * HIDn,
                                          nullptr, nullptr,
                                          out, nullptr);
}

// round 4
// speedup vs baseline: 3.2356x; 1.7007x over previous
#include <cuda_runtime.h>
#include <cuda_bf16.h>
#include <cstdint>

// Problem constants
#define Bn   4
#define Sn   2048
#define HIDn 2048
#define Hn   16
#define Dn   128
#define Mn   8192  // B*S

// Scratch (allocation-free rule: __device__ globals)
__device__ float g_q  [(size_t)Bn * Hn * Sn * Dn];   // [B,H,S,D]
__device__ float g_ctx[(size_t)Mn * HIDn];           // [B,S,H*D] tf32-rounded
__device__ float g_xr [(size_t)Mn * HIDn];           // x rounded to tf32
__device__ float g_wr [4][(size_t)HIDn * HIDn];      // Wq,Wk,Wv,Wo rounded to tf32

// ---------------------------------------------------------------------------
// helpers
// ---------------------------------------------------------------------------
__device__ __forceinline__ uint32_t smem_u32(const void* p) {
    uint32_t a;
    asm("{ .reg .u64 t; cvta.to.shared.u64 t, %1; cvt.u32.u64 %0, t; }"
        : "=r"(a) : "l"(p));
    return a;
}
__device__ __forceinline__ float tf32r(float x) {
    float y;
    asm("cvt.rn.tf32.f32 %0, %1;" : "=f"(y) : "f"(x));
    return y;
}
__device__ __forceinline__ void cpasync16(uint32_t saddr, const void* g) {
    asm volatile("cp.async.cg.shared.global [%0], [%1], 16;" :: "r"(saddr), "l"(g));
}
__device__ __forceinline__ void mma_tf32(float c[4], const uint32_t a[4], const uint32_t b[2]) {
    asm volatile("mma.sync.aligned.m16n8k8.row.col.f32.tf32.tf32.f32 "
                 "{%0,%1,%2,%3}, {%4,%5,%6,%7}, {%8,%9}, {%0,%1,%2,%3};"
                 : "+f"(c[0]), "+f"(c[1]), "+f"(c[2]), "+f"(c[3])
                 : "r"(a[0]), "r"(a[1]), "r"(a[2]), "r"(a[3]), "r"(b[0]), "r"(b[1]));
}
#define LDMX4(r, addr)                                                                  \
    asm volatile("ldmatrix.sync.aligned.m8n8.x4.shared.b16 {%0,%1,%2,%3}, [%4];"        \
                 : "=r"((r)[0]), "=r"((r)[1]), "=r"((r)[2]), "=r"((r)[3]) : "r"(addr))
#define LDMX2(r, addr)                                                                  \
    asm volatile("ldmatrix.sync.aligned.m8n8.x2.shared.b16 {%0,%1}, [%2];"              \
                 : "=r"((r)[0]), "=r"((r)[1]) : "r"(addr))

// ---------------------------------------------------------------------------
// tf32 rounding prepass (RN, unbiased)
// ---------------------------------------------------------------------------
__global__ void __launch_bounds__(256) round_tf32(const float4* __restrict__ in,
                                                  float4* __restrict__ out, int n4) {
    int i = blockIdx.x * blockDim.x + threadIdx.x;
    if (i < n4) {
        float4 v = in[i];
        v.x = tf32r(v.x); v.y = tf32r(v.y); v.z = tf32r(v.z); v.w = tf32r(v.w);
        out[i] = v;
    }
}

// ---------------------------------------------------------------------------
// tf32 mma.sync NT-GEMM (unchanged from R3, proven)
// ---------------------------------------------------------------------------
#define LDW 36
#define TILE_F (128 * LDW)
#define STAGE_F (2 * TILE_F)
#define GEMM_SMEM (2 * STAGE_F * 4)

template<int MODE>
__global__ void __launch_bounds__(256, 2) gemm_mma(const float* __restrict__ A_,
                                                   const float* __restrict__ W0,
                                                   const float* __restrict__ W1,
                                                   const float* __restrict__ W2,
                                                   float* __restrict__ qout,
                                                   float* __restrict__ kvout)
{
    extern __shared__ float sm[];

    const int tid  = threadIdx.x;
    const int wid  = tid >> 5;
    const int lane = tid & 31;
    const int wm = (wid >> 2) * 64;
    const int wn = (wid & 3) * 32;

    const int m0 = blockIdx.y * 128;
    const int n0 = blockIdx.x * 128;
    int z = 0;
    const float* W = W0;
    if (MODE == 0) { z = blockIdx.z; W = (z == 0) ? W0 : (z == 1) ? W1 : W2; }

    const int amat = lane >> 3, arow = lane & 7;
    const int a_r = (amat & 1) * 8 + arow;
    const int a_c = (amat >> 1) * 4;
    const int b_r = lane & 7;
    const int b_c = ((lane >> 3) & 1) * 4;

    float acc[4][4][4] = {};

    auto load_stage = [&](int j, int st) {
        float* As = sm + st * STAGE_F;
        float* Bs = As + TILE_F;
        const int k0 = j * 32;
        #pragma unroll
        for (int i = 0; i < 4; i++) {
            int idx = tid + i * 256;
            int row = idx >> 3;
            int c   = idx & 7;
            cpasync16(smem_u32(As + row * LDW + c * 4),
                      A_ + (size_t)(m0 + row) * HIDn + k0 + c * 4);
            cpasync16(smem_u32(Bs + row * LDW + c * 4),
                      W  + (size_t)(n0 + row) * HIDn + k0 + c * 4);
        }
        asm volatile("cp.async.commit_group;");
    };

    const int nk = HIDn / 32;
    load_stage(0, 0);

    for (int j = 0; j < nk; j++) {
        if (j + 1 < nk) {
            load_stage(j + 1, (j + 1) & 1);
            asm volatile("cp.async.wait_group 1;" ::: "memory");
        } else {
            asm volatile("cp.async.wait_group 0;" ::: "memory");
        }
        __syncthreads();

        const float* As = sm + (j & 1) * STAGE_F;
        const float* Bs = As + TILE_F;

        #pragma unroll
        for (int ks = 0; ks < 4; ks++) {
            const int k0 = ks * 8;
            uint32_t a[4][4];
            #pragma unroll
            for (int i = 0; i < 4; i++) {
                uint32_t ad = smem_u32(As + (wm + i * 16 + a_r) * LDW + k0 + a_c);
                LDMX4(a[i], ad);
            }
            uint32_t b[4][2];
            #pragma unroll
            for (int t = 0; t < 4; t++) {
                uint32_t bd = smem_u32(Bs + (wn + t * 8 + b_r) * LDW + k0 + b_c);
                LDMX2(b[t], bd);
            }
            #pragma unroll
            for (int i = 0; i < 4; i++)
                #pragma unroll
                for (int t = 0; t < 4; t++)
                    mma_tf32(acc[i][t], a[i], b[t]);
        }
        __syncthreads();
    }

    const int er = lane >> 2;
    const int ec = (lane & 3) * 2;

    #pragma unroll
    for (int i = 0; i < 4; i++) {
        const int r0 = m0 + wm + i * 16 + er;
        #pragma unroll
        for (int half = 0; half < 2; half++) {
            const int m = r0 + half * 8;
            if (MODE == 1) {
                size_t o = (size_t)m * HIDn + n0 + wn + ec;
                #pragma unroll
                for (int t = 0; t < 4; t++) {
                    float2 v = make_float2(acc[i][t][half * 2], acc[i][t][half * 2 + 1]);
                    *reinterpret_cast<float2*>(qout + o + t * 8) = v;
                }
            } else {
                const int b = m >> 11;
                const int s = m & (Sn - 1);
                const int h = n0 >> 7;
                float* dst;
                size_t bi;
                if (z == 0) { dst = qout;  bi = (((size_t)(b * Hn + h)) * Sn + s) * Dn; }
                else        { dst = kvout; bi = ((((size_t)(b * Hn + h)) * 2 + (z - 1)) * Sn + s) * Dn; }
                bi += wn + ec;
                #pragma unroll
                for (int t = 0; t < 4; t++) {
                    float2 v = make_float2(acc[i][t][half * 2], acc[i][t][half * 2 + 1]);
                    *reinterpret_cast<float2*>(dst + bi + t * 8) = v;
                }
            }
        }
    }
}

// ---------------------------------------------------------------------------
// Tensor-core causal flash attention (tf32 mma.sync).
// CTA: 128 q-rows, 256 threads = 8 warps x 16 rows. Key tiles of 64.
// QK^T: Q frags in regs (16 k-steps), K row-major smem (B operand).
// PV:   P staged hi/lo in smem (fp32-accurate), V d-major smem (B operand).
// ---------------------------------------------------------------------------
#define LDK 132
#define LDV 68
#define LDP 68
#define OFF_KS  0
#define OFF_VST (64 * LDK)                 // 8448
#define OFF_PSH (OFF_VST + 128 * LDV)      // 17152
#define OFF_PSL (OFF_PSH + 128 * LDP)      // 25856
#define ATT_SMEM_F (OFF_PSL + 128 * LDP)   // 34560 floats
#define ATT_SMEM_B (ATT_SMEM_F * 4)        // 138240 bytes

__global__ void __launch_bounds__(256, 1) attn_mma(const float* __restrict__ q,
                                                   const float* __restrict__ kv,
                                                   float* __restrict__ ctx)
{
    extern __shared__ __align__(16) float sm[];
    float* Ks  = sm + OFF_KS;    // [64][LDK]  rows=key, cols=d
    float* Vst = sm + OFF_VST;   // [128][LDV] rows=d,   cols=key
    float* Psh = sm + OFF_PSH;   // [128][LDP] rows=qrow, cols=key
    float* Psl = sm + OFF_PSL;
    float* Qs  = sm;             // [128][LDK] prologue only (overlaps Ks/Vst)

    const int q0 = blockIdx.x * 128;
    const int bh = blockIdx.y;
    const float* qb = q  + (size_t)bh * Sn * Dn;
    const float* kb = kv + (size_t)bh * 2 * Sn * Dn;
    const float* vb = kb + (size_t)Sn * Dn;

    const int tid  = threadIdx.x;
    const int wid  = tid >> 5;
    const int lane = tid & 31;
    const int w16  = wid * 16;

    // fragment lane maps (validated in gemm_mma)
    const int amat = lane >> 3;
    const int a_r  = (amat & 1) * 8 + (lane & 7);
    const int a_c  = (amat >> 1) * 4;
    const int b_r  = lane & 7;
    const int b_co = (amat & 1) * 4 + (amat >> 1) * 8;   // x4 B: m2,m3 = next k-step

    // ---- prologue: Q tile -> smem (tf32-rounded) -> register fragments ----
    #pragma unroll
    for (int i = 0; i < 16; i++) {
        int idx = tid + i * 256;        // 0..4095 float4s
        int row = idx >> 5;             // 0..127
        int d4  = (idx & 31) * 4;
        float4 v = *reinterpret_cast<const float4*>(qb + (size_t)(q0 + row) * Dn + d4);
        Qs[row * LDK + d4 + 0] = tf32r(v.x);
        Qs[row * LDK + d4 + 1] = tf32r(v.y);
        Qs[row * LDK + d4 + 2] = tf32r(v.z);
        Qs[row * LDK + d4 + 3] = tf32r(v.w);
    }
    __syncthreads();

    uint32_t qa[16][4];
    #pragma unroll
    for (int ks = 0; ks < 16; ks++) {
        uint32_t ad = smem_u32(Qs + (w16 + a_r) * LDK + ks * 8 + a_c);
        LDMX4(qa[ks], ad);
    }

    float acc[16][4] = {};
    float m0r = -1e30f, m1r = -1e30f, l0r = 0.0f, l1r = 0.0f;
    const float scale = 0.08838834764831845f;
    const int r0 = lane >> 2;
    const int qg0 = q0 + w16 + r0;
    const int qg1 = qg0 + 8;
    const int nkt = (q0 >> 6) + 2;

    for (int jt = 0; jt < nkt; jt++) {
        const int j0 = jt * 64;
        __syncthreads();   // prior tile's Ks/Vst reads (and prologue Qs reads) done

        // ---- load K (row-major) and V (d-major), tf32-rounded ----
        #pragma unroll
        for (int i = 0; i < 8; i++) {
            int idx = tid + i * 256;    // 0..2047 float4s
            int row = idx >> 5;         // 0..63 key
            int d4  = (idx & 31) * 4;
            float4 kvec = *reinterpret_cast<const float4*>(kb + (size_t)(j0 + row) * Dn + d4);
            Ks[row * LDK + d4 + 0] = tf32r(kvec.x);
            Ks[row * LDK + d4 + 1] = tf32r(kvec.y);
            Ks[row * LDK + d4 + 2] = tf32r(kvec.z);
            Ks[row * LDK + d4 + 3] = tf32r(kvec.w);
            float4 vvec = *reinterpret_cast<const float4*>(vb + (size_t)(j0 + row) * Dn + d4);
            Vst[(d4 + 0) * LDV + row] = tf32r(vvec.x);
            Vst[(d4 + 1) * LDV + row] = tf32r(vvec.y);
            Vst[(d4 + 2) * LDV + row] = tf32r(vvec.z);
            Vst[(d4 + 3) * LDV + row] = tf32r(vvec.w);
        }
        __syncthreads();

        // ---- scores = Q K^T  (8 n-tiles x 16 k-steps) ----
        float sc[8][4] = {};
        #pragma unroll
        for (int kp = 0; kp < 8; kp++) {
            #pragma unroll
            for (int t = 0; t < 8; t++) {
                uint32_t b4[4];
                LDMX4(b4, smem_u32(Ks + (t * 8 + b_r) * LDK + kp * 16 + b_co));
                mma_tf32(sc[t], qa[2 * kp],     &b4[0]);
                mma_tf32(sc[t], qa[2 * kp + 1], &b4[2]);
            }
        }

        // ---- scale + causal mask ----
        if (j0 + 63 > q0 + w16) {
            #pragma unroll
            for (int t = 0; t < 8; t++) {
                int c0 = j0 + t * 8 + (lane & 3) * 2;
                sc[t][0] = (c0     <= qg0) ? sc[t][0] * scale : -1e30f;
                sc[t][1] = (c0 + 1 <= qg0) ? sc[t][1] * scale : -1e30f;
                sc[t][2] = (c0     <= qg1) ? sc[t][2] * scale : -1e30f;
                sc[t][3] = (c0 + 1 <= qg1) ? sc[t][3] * scale : -1e30f;
            }
        } else {
            #pragma unroll
            for (int t = 0; t < 8; t++) {
                sc[t][0] *= scale; sc[t][1] *= scale;
                sc[t][2] *= scale; sc[t][3] *= scale;
            }
        }

        // ---- online softmax ----
        float mx0 = -1e30f, mx1 = -1e30f;
        #pragma unroll
        for (int t = 0; t < 8; t++) {
            mx0 = fmaxf(mx0, fmaxf(sc[t][0], sc[t][1]));
            mx1 = fmaxf(mx1, fmaxf(sc[t][2], sc[t][3]));
        }
        mx0 = fmaxf(mx0, __shfl_xor_sync(0xffffffffu, mx0, 1));
        mx0 = fmaxf(mx0, __shfl_xor_sync(0xffffffffu, mx0, 2));
        mx1 = fmaxf(mx1, __shfl_xor_sync(0xffffffffu, mx1, 1));
        mx1 = fmaxf(mx1, __shfl_xor_sync(0xffffffffu, mx1, 2));

        float nm0 = fmaxf(m0r, mx0), nm1 = fmaxf(m1r, mx1);
        float al0 = __expf(m0r - nm0), al1 = __expf(m1r - nm1);
        m0r = nm0; m1r = nm1;

        float s0 = 0.0f, s1 = 0.0f;
        #pragma unroll
        for (int t = 0; t < 8; t++) {
            sc[t][0] = __expf(sc[t][0] - nm0);
            sc[t][1] = __expf(sc[t][1] - nm0);
            sc[t][2] = __expf(sc[t][2] - nm1);
            sc[t][3] = __expf(sc[t][3] - nm1);
            s0 += sc[t][0] + sc[t][1];
            s1 += sc[t][2] + sc[t][3];
        }
        s0 += __shfl_xor_sync(0xffffffffu, s0, 1);
        s0 += __shfl_xor_sync(0xffffffffu, s0, 2);
        s1 += __shfl_xor_sync(0xffffffffu, s1, 1);
        s1 += __shfl_xor_sync(0xffffffffu, s1, 2);
        l0r = l0r * al0 + s0;
        l1r = l1r * al1 + s1;

        #pragma unroll
        for (int t = 0; t < 16; t++) {
            acc[t][0] *= al0; acc[t][1] *= al0;
            acc[t][2] *= al1; acc[t][3] *= al1;
        }

        // ---- stage P (hi/lo split: fp32-accurate PV) ----
        const int pc = (lane & 3) * 2;
        #pragma unroll
        for (int t = 0; t < 8; t++) {
            float h0 = tf32r(sc[t][0]), h1 = tf32r(sc[t][1]);
            float h2 = tf32r(sc[t][2]), h3 = tf32r(sc[t][3]);
            *reinterpret_cast<float2*>(Psh + (w16 + r0)     * LDP + t * 8 + pc) = make_float2(h0, h1);
            *reinterpret_cast<float2*>(Psh + (w16 + r0 + 8) * LDP + t * 8 + pc) = make_float2(h2, h3);
            *reinterpret_cast<float2*>(Psl + (w16 + r0)     * LDP + t * 8 + pc) = make_float2(sc[t][0] - h0, sc[t][1] - h1);
            *reinterpret_cast<float2*>(Psl + (w16 + r0 + 8) * LDP + t * 8 + pc) = make_float2(sc[t][2] - h2, sc[t][3] - h3);
        }
        __syncwarp();

        // ---- acc += P V  (16 n-tiles over d, 8 k-steps over keys) ----
        #pragma unroll
        for (int kp = 0; kp < 4; kp++) {
            uint32_t ah0[4], ah1[4], al0f[4], al1f[4];
            LDMX4(ah0,  smem_u32(Psh + (w16 + a_r) * LDP + kp * 16 +     a_c));
            LDMX4(ah1,  smem_u32(Psh + (w16 + a_r) * LDP + kp * 16 + 8 + a_c));
            LDMX4(al0f, smem_u32(Psl + (w16 + a_r) * LDP + kp * 16 +     a_c));
            LDMX4(al1f, smem_u32(Psl + (w16 + a_r) * LDP + kp * 16 + 8 + a_c));
            #pragma unroll
            for (int t = 0; t < 16; t++) {
                uint32_t b4[4];
                LDMX4(b4, smem_u32(Vst + (t * 8 + b_r) * LDV + kp * 16 + b_co));
                mma_tf32(acc[t], ah0,  &b4[0]);
                mma_tf32(acc[t], ah1,  &b4[2]);
                mma_tf32(acc[t], al0f, &b4[0]);
                mma_tf32(acc[t], al1f, &b4[2]);
            }
        }
    }

    // ---- epilogue: ctx[b][s][h*128 + d], tf32-rounded ----
    const int b = bh >> 4;
    const int h = bh & 15;
    const float inv0 = 1.0f / l0r;
    const float inv1 = 1.0f / l1r;
    size_t base0 = ((size_t)b * Sn + qg0) * (Hn * Dn) + h * Dn + (lane & 3) * 2;
    size_t base1 = ((size_t)b * Sn + qg1) * (Hn * Dn) + h * Dn + (lane & 3) * 2;
    #pragma unroll
    for (int t = 0; t < 16; t++) {
        *reinterpret_cast<float2*>(ctx + base0 + t * 8) =
            make_float2(tf32r(acc[t][0] * inv0), tf32r(acc[t][1] * inv0));
        *reinterpret_cast<float2*>(ctx + base1 + t * 8) =
            make_float2(tf32r(acc[t][2] * inv1), tf32r(acc[t][3] * inv1));
    }
}

// ---------------------------------------------------------------------------
// Launch
// ---------------------------------------------------------------------------
extern "C" void kernel_launch(void* const* d_in, const int* in_sizes, int n_in,
                              void* d_out, int out_size)
{
    const float* x  = (const float*)d_in[0];
    const float* Wq = (const float*)d_in[1];
    const float* Wk = (const float*)d_in[2];
    const float* Wv = (const float*)d_in[3];
    const float* Wo = (const float*)d_in[4];

    float* out = (float*)d_out;                    // [B,S,HID]
    float* kv  = out + (size_t)Bn * Sn * HIDn;     // [B,H,2,S,D]

    float* qs;  cudaGetSymbolAddress((void**)&qs,  g_q);
    float* ctx; cudaGetSymbolAddress((void**)&ctx, g_ctx);
    float* xr;  cudaGetSymbolAddress((void**)&xr,  g_xr);
    float* wr;  cudaGetSymbolAddress((void**)&wr,  g_wr);

    // 0) round inputs to tf32 (RN)
    {
        int n4x = Mn * HIDn / 4;
        int n4w = HIDn * HIDn / 4;
        round_tf32<<<(n4x + 255) / 256, 256>>>((const float4*)x,  (float4*)xr, n4x);
        round_tf32<<<(n4w + 255) / 256, 256>>>((const float4*)Wq, (float4*)(wr + 0 * (size_t)HIDn * HIDn), n4w);
        round_tf32<<<(n4w + 255) / 256, 256>>>((const float4*)Wk, (float4*)(wr + 1 * (size_t)HIDn * HIDn), n4w);
        round_tf32<<<(n4w + 255) / 256, 256>>>((const float4*)Wv, (float4*)(wr + 2 * (size_t)HIDn * HIDn), n4w);
        round_tf32<<<(n4w + 255) / 256, 256>>>((const float4*)Wo, (float4*)(wr + 3 * (size_t)HIDn * HIDn), n4w);
    }

    // 1) Q/K/V projections (K,V straight into kv-cache output region)
    cudaFuncSetAttribute(gemm_mma<0>, cudaFuncAttributeMaxDynamicSharedMemorySize, GEMM_SMEM);
    cudaFuncSetAttribute(gemm_mma<1>, cudaFuncAttributeMaxDynamicSharedMemorySize, GEMM_SMEM);
    dim3 gproj(HIDn / 128, Mn / 128, 3);
    gemm_mma<0><<<gproj, 256, GEMM_SMEM>>>(xr,
                                           wr + 0 * (size_t)HIDn * HIDn,
                                           wr + 1 * (size_t)HIDn * HIDn,
                                           wr + 2 * (size_t)HIDn * HIDn,
                                           qs, kv);

    // 2) causal flash attention (tensor cores)
    cudaFuncSetAttribute(attn_mma, cudaFuncAttributeMaxDynamicSharedMemorySize, ATT_SMEM_B);
    dim3 gattn(Sn / 128, Bn * Hn);
    attn_mma<<<gattn, 256, ATT_SMEM_B>>>(qs, kv, ctx);

    // 3) output projection
    dim3 gout(HIDn / 128, Mn / 128, 1);
    gemm_mma<1><<<gout, 256, GEMM_SMEM>>>(ctx,
                                          wr + 3 * (size_t)HIDn * HIDn,
                                          nullptr, nullptr,
                                          out, nullptr);
}

// round 5
// speedup vs baseline: 3.6147x; 1.1172x over previous
#include <cuda_runtime.h>
#include <cuda_bf16.h>
#include <cstdint>

// Problem constants
#define Bn   4
#define Sn   2048
#define HIDn 2048
#define Hn   16
#define Dn   128
#define Mn   8192  // B*S

// Scratch (allocation-free rule: __device__ globals)
__device__ float g_q  [(size_t)Bn * Hn * Sn * Dn];   // [B,H,S,D]
__device__ float g_ctx[(size_t)Mn * HIDn];           // [B,S,H*D] tf32-rounded
__device__ float g_xr [(size_t)Mn * HIDn];           // x rounded to tf32
__device__ float g_wr [4][(size_t)HIDn * HIDn];      // Wq,Wk,Wv,Wo rounded to tf32

// ---------------------------------------------------------------------------
// helpers
// ---------------------------------------------------------------------------
__device__ __forceinline__ uint32_t smem_u32(const void* p) {
    uint32_t a;
    asm("{ .reg .u64 t; cvta.to.shared.u64 t, %1; cvt.u32.u64 %0, t; }"
        : "=r"(a) : "l"(p));
    return a;
}
__device__ __forceinline__ float tf32r(float x) {
    float y;
    asm("cvt.rn.tf32.f32 %0, %1;" : "=f"(y) : "f"(x));
    return y;
}
__device__ __forceinline__ void cpasync16(uint32_t saddr, const void* g) {
    asm volatile("cp.async.cg.shared.global [%0], [%1], 16;" :: "r"(saddr), "l"(g));
}
__device__ __forceinline__ void mma_tf32(float c[4], const uint32_t a[4], const uint32_t b[2]) {
    asm volatile("mma.sync.aligned.m16n8k8.row.col.f32.tf32.tf32.f32 "
                 "{%0,%1,%2,%3}, {%4,%5,%6,%7}, {%8,%9}, {%0,%1,%2,%3};"
                 : "+f"(c[0]), "+f"(c[1]), "+f"(c[2]), "+f"(c[3])
                 : "r"(a[0]), "r"(a[1]), "r"(a[2]), "r"(a[3]), "r"(b[0]), "r"(b[1]));
}
#define LDMX4(r, addr)                                                                  \
    asm volatile("ldmatrix.sync.aligned.m8n8.x4.shared.b16 {%0,%1,%2,%3}, [%4];"        \
                 : "=r"((r)[0]), "=r"((r)[1]), "=r"((r)[2]), "=r"((r)[3]) : "r"(addr))

// ---------------------------------------------------------------------------
// tf32 rounding prepass (RN, unbiased)
// ---------------------------------------------------------------------------
__global__ void __launch_bounds__(256) round_tf32(const float4* __restrict__ in,
                                                  float4* __restrict__ out, int n4) {
    int i = blockIdx.x * blockDim.x + threadIdx.x;
    if (i < n4) {
        float4 v = in[i];
        v.x = tf32r(v.x); v.y = tf32r(v.y); v.z = tf32r(v.z); v.w = tf32r(v.w);
        out[i] = v;
    }
}

// ---------------------------------------------------------------------------
// tf32 mma.sync NT-GEMM: C[128x128] tile of A[M,2048] * W[N,2048]^T
// 256 threads = 8 warps (2m x 4n), warp tile 64x32, BK=32.
// 3-stage cp.async pipeline, ONE __syncthreads per K-iter.
// B fragments via ldmatrix.x4 (two n-tiles per instruction).
// ---------------------------------------------------------------------------
#define LDW 36
#define TILE_F (128 * LDW)
#define STAGE_F (2 * TILE_F)
#define NSTG 3
#define GEMM_SMEM (NSTG * STAGE_F * 4)   // 110592 B

template<int MODE>
__global__ void __launch_bounds__(256, 2) gemm_mma(const float* __restrict__ A_,
                                                   const float* __restrict__ W0,
                                                   const float* __restrict__ W1,
                                                   const float* __restrict__ W2,
                                                   float* __restrict__ qout,
                                                   float* __restrict__ kvout)
{
    extern __shared__ float sm[];

    const int tid  = threadIdx.x;
    const int wid  = tid >> 5;
    const int lane = tid & 31;
    const int wm = (wid >> 2) * 64;
    const int wn = (wid & 3) * 32;

    const int m0 = blockIdx.y * 128;
    const int n0 = blockIdx.x * 128;
    int z = 0;
    const float* W = W0;
    if (MODE == 0) { z = blockIdx.z; W = (z == 0) ? W0 : (z == 1) ? W1 : W2; }

    const int amat = lane >> 3;
    const int a_r = (amat & 1) * 8 + (lane & 7);
    const int a_c = (amat >> 1) * 4;
    // B x4 lane map: groups {0,1}=n-tile pair lo (k halves), {2,3}=n-tile pair hi
    const int bx_r = (lane >> 4) * 8 + (lane & 7);
    const int bx_c = ((lane >> 3) & 1) * 4;

    float acc[4][4][4] = {};

    auto load_stage = [&](int j) {
        float* As = sm + (j % NSTG) * STAGE_F;
        float* Bs = As + TILE_F;
        const int k0 = j * 32;
        #pragma unroll
        for (int i = 0; i < 4; i++) {
            int idx = tid + i * 256;
            int row = idx >> 3;
            int c   = idx & 7;
            cpasync16(smem_u32(As + row * LDW + c * 4),
                      A_ + (size_t)(m0 + row) * HIDn + k0 + c * 4);
            cpasync16(smem_u32(Bs + row * LDW + c * 4),
                      W  + (size_t)(n0 + row) * HIDn + k0 + c * 4);
        }
        asm volatile("cp.async.commit_group;");
    };

    const int nk = HIDn / 32;                    // 64
    load_stage(0);
    load_stage(1);

    for (int j = 0; j < nk; j++) {
        if (j < nk - 2) {
            asm volatile("cp.async.wait_group 1;" ::: "memory");
        } else {
            asm volatile("cp.async.wait_group 0;" ::: "memory");
        }
        __syncthreads();
        if (j + 2 < nk) load_stage(j + 2);       // writes slot freed by this barrier

        const float* As = sm + (j % NSTG) * STAGE_F;
        const float* Bs = As + TILE_F;

        #pragma unroll
        for (int ks = 0; ks < 4; ks++) {
            const int k0 = ks * 8;
            uint32_t a[4][4];
            #pragma unroll
            for (int i = 0; i < 4; i++)
                LDMX4(a[i], smem_u32(As + (wm + i * 16 + a_r) * LDW + k0 + a_c));
            uint32_t b4[2][4];
            #pragma unroll
            for (int tp = 0; tp < 2; tp++)
                LDMX4(b4[tp], smem_u32(Bs + (wn + tp * 16 + bx_r) * LDW + k0 + bx_c));
            #pragma unroll
            for (int i = 0; i < 4; i++)
                #pragma unroll
                for (int t = 0; t < 4; t++)
                    mma_tf32(acc[i][t], a[i], &b4[t >> 1][(t & 1) * 2]);
        }
    }

    const int er = lane >> 2;
    const int ec = (lane & 3) * 2;

    #pragma unroll
    for (int i = 0; i < 4; i++) {
        const int r0 = m0 + wm + i * 16 + er;
        #pragma unroll
        for (int half = 0; half < 2; half++) {
            const int m = r0 + half * 8;
            if (MODE == 1) {
                size_t o = (size_t)m * HIDn + n0 + wn + ec;
                #pragma unroll
                for (int t = 0; t < 4; t++) {
                    float2 v = make_float2(acc[i][t][half * 2], acc[i][t][half * 2 + 1]);
                    *reinterpret_cast<float2*>(qout + o + t * 8) = v;
                }
            } else {
                const int b = m >> 11;
                const int s = m & (Sn - 1);
                const int h = n0 >> 7;
                float* dst;
                size_t bi;
                if (z == 0) { dst = qout;  bi = (((size_t)(b * Hn + h)) * Sn + s) * Dn; }
                else        { dst = kvout; bi = ((((size_t)(b * Hn + h)) * 2 + (z - 1)) * Sn + s) * Dn; }
                bi += wn + ec;
                #pragma unroll
                for (int t = 0; t < 4; t++) {
                    float2 v = make_float2(acc[i][t][half * 2], acc[i][t][half * 2 + 1]);
                    *reinterpret_cast<float2*>(dst + bi + t * 8) = v;
                }
            }
        }
    }
}

// ---------------------------------------------------------------------------
// Tensor-core causal flash attention (tf32 mma.sync).
// CTA: 128 q-rows, 256 threads = 8 warps x 16 rows. Key tiles of 64.
// PV uses tf32-rounded P directly (no lo-split): 256 MMAs/warp/tile.
// ---------------------------------------------------------------------------
#define LDK 132
#define LDV 68
#define LDP 68
#define OFF_KS  0
#define OFF_VST (64 * LDK)                 // 8448
#define OFF_PSH (OFF_VST + 128 * LDV)      // 17152
#define ATT_SMEM_F (OFF_PSH + 128 * LDP)   // 25856 floats
#define ATT_SMEM_B (ATT_SMEM_F * 4)        // 103424 bytes

__global__ void __launch_bounds__(256, 1) attn_mma(const float* __restrict__ q,
                                                   const float* __restrict__ kv,
                                                   float* __restrict__ ctx)
{
    extern __shared__ __align__(16) float sm[];
    float* Ks  = sm + OFF_KS;    // [64][LDK]  rows=key, cols=d
    float* Vst = sm + OFF_VST;   // [128][LDV] rows=d,   cols=key
    float* Psh = sm + OFF_PSH;   // [128][LDP] rows=qrow, cols=key
    float* Qs  = sm;             // [128][LDK] prologue only (overlaps Ks/Vst)

    const int q0 = blockIdx.x * 128;
    const int bh = blockIdx.y;
    const float* qb = q  + (size_t)bh * Sn * Dn;
    const float* kb = kv + (size_t)bh * 2 * Sn * Dn;
    const float* vb = kb + (size_t)Sn * Dn;

    const int tid  = threadIdx.x;
    const int wid  = tid >> 5;
    const int lane = tid & 31;
    const int w16  = wid * 16;

    const int amat = lane >> 3;
    const int a_r  = (amat & 1) * 8 + (lane & 7);
    const int a_c  = (amat >> 1) * 4;
    const int b_r  = lane & 7;
    const int b_co = (amat & 1) * 4 + (amat >> 1) * 8;   // x4 B: m2,m3 = next k-step

    // ---- prologue: Q tile -> smem (tf32-rounded) -> register fragments ----
    #pragma unroll
    for (int i = 0; i < 16; i++) {
        int idx = tid + i * 256;
        int row = idx >> 5;
        int d4  = (idx & 31) * 4;
        float4 v = *reinterpret_cast<const float4*>(qb + (size_t)(q0 + row) * Dn + d4);
        Qs[row * LDK + d4 + 0] = tf32r(v.x);
        Qs[row * LDK + d4 + 1] = tf32r(v.y);
        Qs[row * LDK + d4 + 2] = tf32r(v.z);
        Qs[row * LDK + d4 + 3] = tf32r(v.w);
    }
    __syncthreads();

    uint32_t qa[16][4];
    #pragma unroll
    for (int ks = 0; ks < 16; ks++)
        LDMX4(qa[ks], smem_u32(Qs + (w16 + a_r) * LDK + ks * 8 + a_c));

    float acc[16][4] = {};
    float m0r = -1e30f, m1r = -1e30f, l0r = 0.0f, l1r = 0.0f;
    const float scale = 0.08838834764831845f;
    const int r0 = lane >> 2;
    const int qg0 = q0 + w16 + r0;
    const int qg1 = qg0 + 8;
    const int nkt = (q0 >> 6) + 2;

    for (int jt = 0; jt < nkt; jt++) {
        const int j0 = jt * 64;
        __syncthreads();

        #pragma unroll
        for (int i = 0; i < 8; i++) {
            int idx = tid + i * 256;
            int row = idx >> 5;
            int d4  = (idx & 31) * 4;
            float4 kvec = *reinterpret_cast<const float4*>(kb + (size_t)(j0 + row) * Dn + d4);
            Ks[row * LDK + d4 + 0] = tf32r(kvec.x);
            Ks[row * LDK + d4 + 1] = tf32r(kvec.y);
            Ks[row * LDK + d4 + 2] = tf32r(kvec.z);
            Ks[row * LDK + d4 + 3] = tf32r(kvec.w);
            float4 vvec = *reinterpret_cast<const float4*>(vb + (size_t)(j0 + row) * Dn + d4);
            Vst[(d4 + 0) * LDV + row] = tf32r(vvec.x);
            Vst[(d4 + 1) * LDV + row] = tf32r(vvec.y);
            Vst[(d4 + 2) * LDV + row] = tf32r(vvec.z);
            Vst[(d4 + 3) * LDV + row] = tf32r(vvec.w);
        }
        __syncthreads();

        // ---- scores = Q K^T ----
        float sc[8][4] = {};
        #pragma unroll
        for (int kp = 0; kp < 8; kp++) {
            #pragma unroll
            for (int t = 0; t < 8; t++) {
                uint32_t b4[4];
                LDMX4(b4, smem_u32(Ks + (t * 8 + b_r) * LDK + kp * 16 + b_co));
                mma_tf32(sc[t], qa[2 * kp],     &b4[0]);
                mma_tf32(sc[t], qa[2 * kp + 1], &b4[2]);
            }
        }

        // ---- scale + causal mask ----
        if (j0 + 63 > q0 + w16) {
            #pragma unroll
            for (int t = 0; t < 8; t++) {
                int c0 = j0 + t * 8 + (lane & 3) * 2;
                sc[t][0] = (c0     <= qg0) ? sc[t][0] * scale : -1e30f;
                sc[t][1] = (c0 + 1 <= qg0) ? sc[t][1] * scale : -1e30f;
                sc[t][2] = (c0     <= qg1) ? sc[t][2] * scale : -1e30f;
                sc[t][3] = (c0 + 1 <= qg1) ? sc[t][3] * scale : -1e30f;
            }
        } else {
            #pragma unroll
            for (int t = 0; t < 8; t++) {
                sc[t][0] *= scale; sc[t][1] *= scale;
                sc[t][2] *= scale; sc[t][3] *= scale;
            }
        }

        // ---- online softmax ----
        float mx0 = -1e30f, mx1 = -1e30f;
        #pragma unroll
        for (int t = 0; t < 8; t++) {
            mx0 = fmaxf(mx0, fmaxf(sc[t][0], sc[t][1]));
            mx1 = fmaxf(mx1, fmaxf(sc[t][2], sc[t][3]));
        }
        mx0 = fmaxf(mx0, __shfl_xor_sync(0xffffffffu, mx0, 1));
        mx0 = fmaxf(mx0, __shfl_xor_sync(0xffffffffu, mx0, 2));
        mx1 = fmaxf(mx1, __shfl_xor_sync(0xffffffffu, mx1, 1));
        mx1 = fmaxf(mx1, __shfl_xor_sync(0xffffffffu, mx1, 2));

        float nm0 = fmaxf(m0r, mx0), nm1 = fmaxf(m1r, mx1);
        float al0 = __expf(m0r - nm0), al1 = __expf(m1r - nm1);
        m0r = nm0; m1r = nm1;

        float s0 = 0.0f, s1 = 0.0f;
        #pragma unroll
        for (int t = 0; t < 8; t++) {
            sc[t][0] = __expf(sc[t][0] - nm0);
            sc[t][1] = __expf(sc[t][1] - nm0);
            sc[t][2] = __expf(sc[t][2] - nm1);
            sc[t][3] = __expf(sc[t][3] - nm1);
            s0 += sc[t][0] + sc[t][1];
            s1 += sc[t][2] + sc[t][3];
        }
        s0 += __shfl_xor_sync(0xffffffffu, s0, 1);
        s0 += __shfl_xor_sync(0xffffffffu, s0, 2);
        s1 += __shfl_xor_sync(0xffffffffu, s1, 1);
        s1 += __shfl_xor_sync(0xffffffffu, s1, 2);
        l0r = l0r * al0 + s0;
        l1r = l1r * al1 + s1;

        #pragma unroll
        for (int t = 0; t < 16; t++) {
            acc[t][0] *= al0; acc[t][1] *= al0;
            acc[t][2] *= al1; acc[t][3] *= al1;
        }

        // ---- stage P (tf32-rounded, own warp's rows only) ----
        const int pc = (lane & 3) * 2;
        #pragma unroll
        for (int t = 0; t < 8; t++) {
            *reinterpret_cast<float2*>(Psh + (w16 + r0)     * LDP + t * 8 + pc) =
                make_float2(tf32r(sc[t][0]), tf32r(sc[t][1]));
            *reinterpret_cast<float2*>(Psh + (w16 + r0 + 8) * LDP + t * 8 + pc) =
                make_float2(tf32r(sc[t][2]), tf32r(sc[t][3]));
        }
        __syncwarp();

        // ---- acc += P V ----
        #pragma unroll
        for (int kp = 0; kp < 4; kp++) {
            uint32_t ah0[4], ah1[4];
            LDMX4(ah0, smem_u32(Psh + (w16 + a_r) * LDP + kp * 16 +     a_c));
            LDMX4(ah1, smem_u32(Psh + (w16 + a_r) * LDP + kp * 16 + 8 + a_c));
            #pragma unroll
            for (int t = 0; t < 16; t++) {
                uint32_t b4[4];
                LDMX4(b4, smem_u32(Vst + (t * 8 + b_r) * LDV + kp * 16 + b_co));
                mma_tf32(acc[t], ah0, &b4[0]);
                mma_tf32(acc[t], ah1, &b4[2]);
            }
        }
    }

    // ---- epilogue: ctx[b][s][h*128 + d], tf32-rounded ----
    const int b = bh >> 4;
    const int h = bh & 15;
    const float inv0 = 1.0f / l0r;
    const float inv1 = 1.0f / l1r;
    size_t base0 = ((size_t)b * Sn + qg0) * (Hn * Dn) + h * Dn + (lane & 3) * 2;
    size_t base1 = ((size_t)b * Sn + qg1) * (Hn * Dn) + h * Dn + (lane & 3) * 2;
    #pragma unroll
    for (int t = 0; t < 16; t++) {
        *reinterpret_cast<float2*>(ctx + base0 + t * 8) =
            make_float2(tf32r(acc[t][0] * inv0), tf32r(acc[t][1] * inv0));
        *reinterpret_cast<float2*>(ctx + base1 + t * 8) =
            make_float2(tf32r(acc[t][2] * inv1), tf32r(acc[t][3] * inv1));
    }
}

// ---------------------------------------------------------------------------
// Launch
// ---------------------------------------------------------------------------
extern "C" void kernel_launch(void* const* d_in, const int* in_sizes, int n_in,
                              void* d_out, int out_size)
{
    const float* x  = (const float*)d_in[0];
    const float* Wq = (const float*)d_in[1];
    const float* Wk = (const float*)d_in[2];
    const float* Wv = (const float*)d_in[3];
    const float* Wo = (const float*)d_in[4];

    float* out = (float*)d_out;                    // [B,S,HID]
    float* kv  = out + (size_t)Bn * Sn * HIDn;     // [B,H,2,S,D]

    float* qs;  cudaGetSymbolAddress((void**)&qs,  g_q);
    float* ctx; cudaGetSymbolAddress((void**)&ctx, g_ctx);
    float* xr;  cudaGetSymbolAddress((void**)&xr,  g_xr);
    float* wr;  cudaGetSymbolAddress((void**)&wr,  g_wr);

    // 0) round inputs to tf32 (RN)
    {
        int n4x = Mn * HIDn / 4;
        int n4w = HIDn * HIDn / 4;
        round_tf32<<<(n4x + 255) / 256, 256>>>((const float4*)x,  (float4*)xr, n4x);
        round_tf32<<<(n4w + 255) / 256, 256>>>((const float4*)Wq, (float4*)(wr + 0 * (size_t)HIDn * HIDn), n4w);
        round_tf32<<<(n4w + 255) / 256, 256>>>((const float4*)Wk, (float4*)(wr + 1 * (size_t)HIDn * HIDn), n4w);
        round_tf32<<<(n4w + 255) / 256, 256>>>((const float4*)Wv, (float4*)(wr + 2 * (size_t)HIDn * HIDn), n4w);
        round_tf32<<<(n4w + 255) / 256, 256>>>((const float4*)Wo, (float4*)(wr + 3 * (size_t)HIDn * HIDn), n4w);
    }

    // 1) Q/K/V projections (K,V straight into kv-cache output region)
    cudaFuncSetAttribute(gemm_mma<0>, cudaFuncAttributeMaxDynamicSharedMemorySize, GEMM_SMEM);
    cudaFuncSetAttribute(gemm_mma<1>, cudaFuncAttributeMaxDynamicSharedMemorySize, GEMM_SMEM);
    dim3 gproj(HIDn / 128, Mn / 128, 3);
    gemm_mma<0><<<gproj, 256, GEMM_SMEM>>>(xr,
                                           wr + 0 * (size_t)HIDn * HIDn,
                                           wr + 1 * (size_t)HIDn * HIDn,
                                           wr + 2 * (size_t)HIDn * HIDn,
                                           qs, kv);

    // 2) causal flash attention (tensor cores)
    cudaFuncSetAttribute(attn_mma, cudaFuncAttributeMaxDynamicSharedMemorySize, ATT_SMEM_B);
    dim3 gattn(Sn / 128, Bn * Hn);
    attn_mma<<<gattn, 256, ATT_SMEM_B>>>(qs, kv, ctx);

    // 3) output projection
    dim3 gout(HIDn / 128, Mn / 128, 1);
    gemm_mma<1><<<gout, 256, GEMM_SMEM>>>(ctx,
                                          wr + 3 * (size_t)HIDn * HIDn,
                                          nullptr, nullptr,
                                          out, nullptr);
}

// round 7
// speedup vs baseline: 6.7428x; 1.8654x over previous
#include <cuda_runtime.h>
#include <cuda_fp16.h>
#include <cstdint>

// Problem constants
#define Bn   4
#define Sn   2048
#define HIDn 2048
#define Hn   16
#define Dn   128
#define Mn   8192  // B*S

// Scratch (allocation-free rule: __device__ globals)
__device__ __half g_xh [(size_t)Mn * HIDn];            // x in fp16
__device__ __half g_wh [4][(size_t)HIDn * HIDn];       // Wq,Wk,Wv,Wo in fp16
__device__ __half g_qh [(size_t)Bn * Hn * Sn * Dn];    // Q fp16 [B,H,S,D]
__device__ __half g_kh [(size_t)Bn * Hn * Sn * Dn];    // K fp16 mirror
__device__ __half g_vh [(size_t)Bn * Hn * Sn * Dn];    // V fp16 mirror
__device__ __half g_ctx[(size_t)Mn * HIDn];            // ctx fp16 [B,S,H*D]

// ---------------------------------------------------------------------------
// helpers
// ---------------------------------------------------------------------------
__device__ __forceinline__ uint32_t smem_u32(const void* p) {
    uint32_t a;
    asm("{ .reg .u64 t; cvta.to.shared.u64 t, %1; cvt.u32.u64 %0, t; }"
        : "=r"(a) : "l"(p));
    return a;
}
__device__ __forceinline__ void cpasync16(uint32_t saddr, const void* g) {
    asm volatile("cp.async.cg.shared.global [%0], [%1], 16;" :: "r"(saddr), "l"(g));
}
__device__ __forceinline__ void mma_f16(float c[4], const uint32_t a[4], const uint32_t b[2]) {
    asm volatile("mma.sync.aligned.m16n8k16.row.col.f32.f16.f16.f32 "
                 "{%0,%1,%2,%3}, {%4,%5,%6,%7}, {%8,%9}, {%0,%1,%2,%3};"
                 : "+f"(c[0]), "+f"(c[1]), "+f"(c[2]), "+f"(c[3])
                 : "r"(a[0]), "r"(a[1]), "r"(a[2]), "r"(a[3]), "r"(b[0]), "r"(b[1]));
}
#define LDMX4(r, addr)                                                                  \
    asm volatile("ldmatrix.sync.aligned.m8n8.x4.shared.b16 {%0,%1,%2,%3}, [%4];"        \
                 : "=r"((r)[0]), "=r"((r)[1]), "=r"((r)[2]), "=r"((r)[3]) : "r"(addr))
#define LDMX4T(r, addr)                                                                 \
    asm volatile("ldmatrix.sync.aligned.m8n8.x4.trans.shared.b16 {%0,%1,%2,%3}, [%4];"  \
                 : "=r"((r)[0]), "=r"((r)[1]), "=r"((r)[2]), "=r"((r)[3]) : "r"(addr))

// ---------------------------------------------------------------------------
// fp32 -> fp16 conversion prepass
// ---------------------------------------------------------------------------
__global__ void __launch_bounds__(256) f2h(const float4* __restrict__ in,
                                           uint2* __restrict__ out, int n4) {
    int i = blockIdx.x * blockDim.x + threadIdx.x;
    if (i < n4) {
        float4 v = in[i];
        __half2 a = __floats2half2_rn(v.x, v.y);
        __half2 b = __floats2half2_rn(v.z, v.w);
        uint2 r;
        r.x = *reinterpret_cast<uint32_t*>(&a);
        r.y = *reinterpret_cast<uint32_t*>(&b);
        out[i] = r;
    }
}

// ---------------------------------------------------------------------------
// fp16 mma.sync NT-GEMM: C[128x128] tile of A[M,2048] * W[N,2048]^T
// 256 threads = 8 warps (2m x 4n), warp tile 64x32, BK=32 (2 k16-steps).
// 3-stage cp.async pipeline, ONE __syncthreads per K-iter.
// MODE 0: QKV projection: z=0 -> Q fp16; z=1/2 -> K/V fp32 to cache + fp16 mirror
// MODE 1: output projection: fp32 out
// ---------------------------------------------------------------------------
#define LDW 40                              // halves per row (80B, conflict-free)
#define TILE_H (128 * LDW)                  // halves
#define STAGE_H (2 * TILE_H)
#define NSTG 3
#define GEMM_SMEM (NSTG * STAGE_H * 2)      // bytes = 61440

template<int MODE>
__global__ void __launch_bounds__(256, 2) gemm_mma(const __half* __restrict__ A_,
                                                   const __half* __restrict__ W0,
                                                   const __half* __restrict__ W1,
                                                   const __half* __restrict__ W2,
                                                   float* __restrict__ fout,
                                                   __half* __restrict__ hq,
                                                   __half* __restrict__ hk,
                                                   __half* __restrict__ hv)
{
    extern __shared__ __half smh[];

    const int tid  = threadIdx.x;
    const int wid  = tid >> 5;
    const int lane = tid & 31;
    const int wm = (wid >> 2) * 64;
    const int wn = (wid & 3) * 32;

    const int m0 = blockIdx.y * 128;
    const int n0 = blockIdx.x * 128;
    int z = 0;
    const __half* W = W0;
    if (MODE == 0) { z = blockIdx.z; W = (z == 0) ? W0 : (z == 1) ? W1 : W2; }

    const int mat = lane >> 3;
    const int a_r = (mat & 1) * 8 + (lane & 7);     // A: m within 16
    const int a_c = (mat >> 1) * 8;                 // A: k-half offset (halves)
    const int bx_r = (lane >> 4) * 8 + (lane & 7);  // B: n within 16 (2 n-tiles)
    const int bx_c = ((lane >> 3) & 1) * 8;         // B: k-half offset

    float acc[4][4][4] = {};

    auto load_stage = [&](int j) {
        __half* As = smh + (j % NSTG) * STAGE_H;
        __half* Bs = As + TILE_H;
        const int k0 = j * 32;
        #pragma unroll
        for (int i = 0; i < 2; i++) {
            int idx = tid + i * 256;                // 0..511
            int row = idx >> 2;                     // 0..127
            int c   = idx & 3;                      // 16B chunk (8 halves)
            cpasync16(smem_u32(As + row * LDW + c * 8),
                      A_ + (size_t)(m0 + row) * HIDn + k0 + c * 8);
            cpasync16(smem_u32(Bs + row * LDW + c * 8),
                      W  + (size_t)(n0 + row) * HIDn + k0 + c * 8);
        }
        asm volatile("cp.async.commit_group;");
    };

    const int nk = HIDn / 32;                       // 64
    load_stage(0);
    load_stage(1);

    for (int j = 0; j < nk; j++) {
        if (j < nk - 2) {
            asm volatile("cp.async.wait_group 1;" ::: "memory");
        } else {
            asm volatile("cp.async.wait_group 0;" ::: "memory");
        }
        __syncthreads();
        if (j + 2 < nk) load_stage(j + 2);

        const __half* As = smh + (j % NSTG) * STAGE_H;
        const __half* Bs = As + TILE_H;

        #pragma unroll
        for (int ks = 0; ks < 2; ks++) {            // 2 x k16
            const int k0 = ks * 16;
            uint32_t a[4][4];
            #pragma unroll
            for (int i = 0; i < 4; i++)
                LDMX4(a[i], smem_u32(As + (wm + i * 16 + a_r) * LDW + k0 + a_c));
            uint32_t b4[2][4];
            #pragma unroll
            for (int tp = 0; tp < 2; tp++)
                LDMX4(b4[tp], smem_u32(Bs + (wn + tp * 16 + bx_r) * LDW + k0 + bx_c));
            #pragma unroll
            for (int i = 0; i < 4; i++)
                #pragma unroll
                for (int t = 0; t < 4; t++)
                    mma_f16(acc[i][t], a[i], &b4[t >> 1][(t & 1) * 2]);
        }
    }

    const int er = lane >> 2;
    const int ec = (lane & 3) * 2;

    #pragma unroll
    for (int i = 0; i < 4; i++) {
        const int r0 = m0 + wm + i * 16 + er;
        #pragma unroll
        for (int half = 0; half < 2; half++) {
            const int m = r0 + half * 8;
            if (MODE == 1) {
                size_t o = (size_t)m * HIDn + n0 + wn + ec;
                #pragma unroll
                for (int t = 0; t < 4; t++) {
                    float2 v = make_float2(acc[i][t][half * 2], acc[i][t][half * 2 + 1]);
                    *reinterpret_cast<float2*>(fout + o + t * 8) = v;
                }
            } else {
                const int b = m >> 11;
                const int s = m & (Sn - 1);
                const int h = n0 >> 7;              // one head per N tile
                const int d0 = wn + ec;
                size_t hb = (((size_t)(b * Hn + h)) * Sn + s) * Dn + d0;
                if (z == 0) {
                    #pragma unroll
                    for (int t = 0; t < 4; t++) {
                        __half2 hv2 = __floats2half2_rn(acc[i][t][half * 2], acc[i][t][half * 2 + 1]);
                        *reinterpret_cast<__half2*>(hq + hb + t * 8) = hv2;
                    }
                } else {
                    size_t fb = ((((size_t)(b * Hn + h)) * 2 + (z - 1)) * Sn + s) * Dn + d0;
                    __half* hm = (z == 1) ? hk : hv;
                    #pragma unroll
                    for (int t = 0; t < 4; t++) {
                        float2 v = make_float2(acc[i][t][half * 2], acc[i][t][half * 2 + 1]);
                        *reinterpret_cast<float2*>(fout + fb + t * 8) = v;
                        __half2 hv2 = __floats2half2_rn(v.x, v.y);
                        *reinterpret_cast<__half2*>(hm + hb + t * 8) = hv2;
                    }
                }
            }
        }
    }
}

// ---------------------------------------------------------------------------
// fp16 tensor-core causal flash attention.
// CTA: 128 q-rows, 256 threads = 8 warps x 16 rows. 64-key tiles.
// QK^T: Q frags in regs (8 k16-steps), K row-major smem.
// PV:   P fp16 in smem (A), V row-major smem read via ldmatrix.trans (B).
// ---------------------------------------------------------------------------
#define LDQ 136
#define LDK 136
#define LDVr 136
#define LDP 72
#define OFF_KS  0
#define OFF_VS  (64 * LDK)                   // 8704 halves
#define OFF_PS  (OFF_VS + 64 * LDVr)         // 17408
#define ATT_SMEM_H (OFF_PS + 128 * LDP)      // 26624 halves
#define ATT_SMEM_B (ATT_SMEM_H * 2)          // 53248 bytes

__global__ void __launch_bounds__(256, 1) attn_mma(const __half* __restrict__ q,
                                                   const __half* __restrict__ kh,
                                                   const __half* __restrict__ vh,
                                                   __half* __restrict__ ctx)
{
    extern __shared__ __half smh[];
    __half* Ks  = smh + OFF_KS;   // [64][LDK]  rows=key, cols=d
    __half* Vs  = smh + OFF_VS;   // [64][LDVr] rows=key, cols=d
    __half* Psh = smh + OFF_PS;   // [128][LDP] rows=qrow, cols=key
    __half* Qs  = smh;            // [128][LDQ] prologue only (overlaps Ks+Vs)

    const int q0 = blockIdx.x * 128;
    const int bh = blockIdx.y;
    const __half* qb = q  + (size_t)bh * Sn * Dn;
    const __half* kb = kh + (size_t)bh * Sn * Dn;
    const __half* vb = vh + (size_t)bh * Sn * Dn;

    const int tid  = threadIdx.x;
    const int wid  = tid >> 5;
    const int lane = tid & 31;
    const int w16  = wid * 16;

    const int mat = lane >> 3;
    const int a_r = (mat & 1) * 8 + (lane & 7);
    const int a_c = (mat >> 1) * 8;
    const int b_r = (lane >> 4) * 8 + (lane & 7);   // B no-trans: n within 16
    const int b_c = ((lane >> 3) & 1) * 8;          // B no-trans: k-half
    const int v_r = ((lane >> 3) & 1) * 8 + (lane & 7);  // V trans: key within 16
    const int v_c = (lane >> 4) * 8;                     // V trans: d-half

    // ---- prologue: Q tile -> smem -> register fragments ----
    #pragma unroll
    for (int i = 0; i < 8; i++) {
        int idx = tid + i * 256;       // 0..2047 chunks of 8 halves
        int row = idx >> 4;            // 0..127
        int c   = idx & 15;
        *reinterpret_cast<float4*>(Qs + row * LDQ + c * 8) =
            *reinterpret_cast<const float4*>(qb + (size_t)(q0 + row) * Dn + c * 8);
    }
    __syncthreads();

    uint32_t qa[8][4];
    #pragma unroll
    for (int ks = 0; ks < 8; ks++)
        LDMX4(qa[ks], smem_u32(Qs + (w16 + a_r) * LDQ + ks * 16 + a_c));

    float acc[16][4] = {};
    float m0r = -1e30f, m1r = -1e30f, l0r = 0.0f, l1r = 0.0f;
    const float scale = 0.08838834764831845f;
    const int r0 = lane >> 2;
    const int pc = (lane & 3) * 2;
    const int qg0 = q0 + w16 + r0;
    const int qg1 = qg0 + 8;
    const int nkt = (q0 >> 6) + 2;

    for (int jt = 0; jt < nkt; jt++) {
        const int j0 = jt * 64;
        __syncthreads();   // prior tile reads (and prologue Q reads) complete

        // ---- load K and V tiles (row-major halves) ----
        #pragma unroll
        for (int i = 0; i < 4; i++) {
            int idx = tid + i * 256;   // 0..1023 chunks
            int row = idx >> 4;        // 0..63
            int c   = idx & 15;
            *reinterpret_cast<float4*>(Ks + row * LDK + c * 8) =
                *reinterpret_cast<const float4*>(kb + (size_t)(j0 + row) * Dn + c * 8);
            *reinterpret_cast<float4*>(Vs + row * LDVr + c * 8) =
                *reinterpret_cast<const float4*>(vb + (size_t)(j0 + row) * Dn + c * 8);
        }
        __syncthreads();

        // ---- scores = Q K^T  (8 n-tiles x 8 k16-steps) ----
        float sc[8][4] = {};
        #pragma unroll
        for (int ks = 0; ks < 8; ks++) {
            uint32_t kb4[4][4];
            #pragma unroll
            for (int tp = 0; tp < 4; tp++)
                LDMX4(kb4[tp], smem_u32(Ks + (tp * 16 + b_r) * LDK + ks * 16 + b_c));
            #pragma unroll
            for (int t = 0; t < 8; t++)
                mma_f16(sc[t], qa[ks], &kb4[t >> 1][(t & 1) * 2]);
        }

        // ---- scale + causal mask ----
        if (j0 + 63 > q0 + w16) {
            #pragma unroll
            for (int t = 0; t < 8; t++) {
                int c0 = j0 + t * 8 + pc;
                sc[t][0] = (c0     <= qg0) ? sc[t][0] * scale : -1e30f;
                sc[t][1] = (c0 + 1 <= qg0) ? sc[t][1] * scale : -1e30f;
                sc[t][2] = (c0     <= qg1) ? sc[t][2] * scale : -1e30f;
                sc[t][3] = (c0 + 1 <= qg1) ? sc[t][3] * scale : -1e30f;
            }
        } else {
            #pragma unroll
            for (int t = 0; t < 8; t++) {
                sc[t][0] *= scale; sc[t][1] *= scale;
                sc[t][2] *= scale; sc[t][3] *= scale;
            }
        }

        // ---- online softmax ----
        float mx0 = -1e30f, mx1 = -1e30f;
        #pragma unroll
        for (int t = 0; t < 8; t++) {
            mx0 = fmaxf(mx0, fmaxf(sc[t][0], sc[t][1]));
            mx1 = fmaxf(mx1, fmaxf(sc[t][2], sc[t][3]));
        }
        mx0 = fmaxf(mx0, __shfl_xor_sync(0xffffffffu, mx0, 1));
        mx0 = fmaxf(mx0, __shfl_xor_sync(0xffffffffu, mx0, 2));
        mx1 = fmaxf(mx1, __shfl_xor_sync(0xffffffffu, mx1, 1));
        mx1 = fmaxf(mx1, __shfl_xor_sync(0xffffffffu, mx1, 2));

        float nm0 = fmaxf(m0r, mx0), nm1 = fmaxf(m1r, mx1);
        float al0 = __expf(m0r - nm0), al1 = __expf(m1r - nm1);
        m0r = nm0; m1r = nm1;

        float s0 = 0.0f, s1 = 0.0f;
        #pragma unroll
        for (int t = 0; t < 8; t++) {
            sc[t][0] = __expf(sc[t][0] - nm0);
            sc[t][1] = __expf(sc[t][1] - nm0);
            sc[t][2] = __expf(sc[t][2] - nm1);
            sc[t][3] = __expf(sc[t][3] - nm1);
            s0 += sc[t][0] + sc[t][1];
            s1 += sc[t][2] + sc[t][3];
        }
        s0 += __shfl_xor_sync(0xffffffffu, s0, 1);
        s0 += __shfl_xor_sync(0xffffffffu, s0, 2);
        s1 += __shfl_xor_sync(0xffffffffu, s1, 1);
        s1 += __shfl_xor_sync(0xffffffffu, s1, 2);
        l0r = l0r * al0 + s0;
        l1r = l1r * al1 + s1;

        #pragma unroll
        for (int t = 0; t < 16; t++) {
            acc[t][0] *= al0; acc[t][1] *= al0;
            acc[t][2] *= al1; acc[t][3] *= al1;
        }

        // ---- stage P (fp16, own warp's rows) ----
        #pragma unroll
        for (int t = 0; t < 8; t++) {
            *reinterpret_cast<__half2*>(Psh + (w16 + r0)     * LDP + t * 8 + pc) =
                __floats2half2_rn(sc[t][0], sc[t][1]);
            *reinterpret_cast<__half2*>(Psh + (w16 + r0 + 8) * LDP + t * 8 + pc) =
                __floats2half2_rn(sc[t][2], sc[t][3]);
        }
        __syncwarp();

        // ---- acc += P V  (A = P, B = V via ldmatrix.trans) ----
        #pragma unroll
        for (int kp = 0; kp < 4; kp++) {
            uint32_t pa[4];
            LDMX4(pa, smem_u32(Psh + (w16 + a_r) * LDP + kp * 16 + a_c));
            #pragma unroll
            for (int dp = 0; dp < 8; dp++) {
                uint32_t vb4[4];
                LDMX4T(vb4, smem_u32(Vs + (kp * 16 + v_r) * LDVr + dp * 16 + v_c));
                mma_f16(acc[dp * 2],     pa, &vb4[0]);
                mma_f16(acc[dp * 2 + 1], pa, &vb4[2]);
            }
        }
    }

    // ---- epilogue: ctx fp16 [b][s][h*128 + d] ----
    const int b = bh >> 4;
    const int h = bh & 15;
    const float inv0 = 1.0f / l0r;
    const float inv1 = 1.0f / l1r;
    size_t base0 = ((size_t)b * Sn + qg0) * (Hn * Dn) + h * Dn + pc;
    size_t base1 = ((size_t)b * Sn + qg1) * (Hn * Dn) + h * Dn + pc;
    #pragma unroll
    for (int t = 0; t < 16; t++) {
        *reinterpret_cast<__half2*>(ctx + base0 + t * 8) =
            __floats2half2_rn(acc[t][0] * inv0, acc[t][1] * inv0);
        *reinterpret_cast<__half2*>(ctx + base1 + t * 8) =
            __floats2half2_rn(acc[t][2] * inv1, acc[t][3] * inv1);
    }
}

// ---------------------------------------------------------------------------
// Launch
// ---------------------------------------------------------------------------
extern "C" void kernel_launch(void* const* d_in, const int* in_sizes, int n_in,
                              void* d_out, int out_size)
{
    const float* x  = (const float*)d_in[0];
    const float* Wq = (const float*)d_in[1];
    const float* Wk = (const float*)d_in[2];
    const float* Wv = (const float*)d_in[3];
    const float* Wo = (const float*)d_in[4];

    float* out = (float*)d_out;                    // [B,S,HID]
    float* kv  = out + (size_t)Bn * Sn * HIDn;     // [B,H,2,S,D]

    __half *xh, *wh, *qh, *kh, *vh, *ctxh;
    cudaGetSymbolAddress((void**)&xh,   g_xh);
    cudaGetSymbolAddress((void**)&wh,   g_wh);
    cudaGetSymbolAddress((void**)&qh,   g_qh);
    cudaGetSymbolAddress((void**)&kh,   g_kh);
    cudaGetSymbolAddress((void**)&vh,   g_vh);
    cudaGetSymbolAddress((void**)&ctxh, g_ctx);

    // 0) convert inputs to fp16
    {
        int n4x = Mn * HIDn / 4;
        int n4w = HIDn * HIDn / 4;
        f2h<<<(n4x + 255) / 256, 256>>>((const float4*)x,  (uint2*)xh, n4x);
        f2h<<<(n4w + 255) / 256, 256>>>((const float4*)Wq, (uint2*)(wh + 0 * (size_t)HIDn * HIDn), n4w);
        f2h<<<(n4w + 255) / 256, 256>>>((const float4*)Wk, (uint2*)(wh + 1 * (size_t)HIDn * HIDn), n4w);
        f2h<<<(n4w + 255) / 256, 256>>>((const float4*)Wv, (uint2*)(wh + 2 * (size_t)HIDn * HIDn), n4w);
        f2h<<<(n4w + 255) / 256, 256>>>((const float4*)Wo, (uint2*)(wh + 3 * (size_t)HIDn * HIDn), n4w);
    }

    // 1) Q/K/V projections (K,V fp32 straight into kv cache + fp16 mirrors)
    cudaFuncSetAttribute(gemm_mma<0>, cudaFuncAttributeMaxDynamicSharedMemorySize, GEMM_SMEM);
    cudaFuncSetAttribute(gemm_mma<1>, cudaFuncAttributeMaxDynamicSharedMemorySize, GEMM_SMEM);
    dim3 gproj(HIDn / 128, Mn / 128, 3);
    gemm_mma<0><<<gproj, 256, GEMM_SMEM>>>(xh,
                                           wh + 0 * (size_t)HIDn * HIDn,
                                           wh + 1 * (size_t)HIDn * HIDn,
                                           wh + 2 * (size_t)HIDn * HIDn,
                                           kv, qh, kh, vh);

    // 2) causal flash attention (fp16 tensor cores)
    cudaFuncSetAttribute(attn_mma, cudaFuncAttributeMaxDynamicSharedMemorySize, ATT_SMEM_B);
    dim3 gattn(Sn / 128, Bn * Hn);
    attn_mma<<<gattn, 256, ATT_SMEM_B>>>(qh, kh, vh, ctxh);

    // 3) output projection (fp32 result)
    dim3 gout(HIDn / 128, Mn / 128, 1);
    gemm_mma<1><<<gout, 256, GEMM_SMEM>>>(ctxh,
                                          wh + 3 * (size_t)HIDn * HIDn,
                                          nullptr, nullptr,
                                          out, nullptr, nullptr, nullptr);
}

// round 8
// speedup vs baseline: 7.0205x; 1.0412x over previous
#include <cuda_runtime.h>
#include <cuda_fp16.h>
#include <cstdint>

// Problem constants
#define Bn   4
#define Sn   2048
#define HIDn 2048
#define Hn   16
#define Dn   128
#define Mn   8192  // B*S

// Scratch (allocation-free rule: __device__ globals)
__device__ __half g_xh [(size_t)Mn * HIDn];            // x in fp16
__device__ __half g_wh [4][(size_t)HIDn * HIDn];       // Wq,Wk,Wv,Wo in fp16
__device__ __half g_qh [(size_t)Bn * Hn * Sn * Dn];    // Q fp16 [B,H,S,D]
__device__ __half g_kh [(size_t)Bn * Hn * Sn * Dn];    // K fp16 mirror
__device__ __half g_vh [(size_t)Bn * Hn * Sn * Dn];    // V fp16 mirror
__device__ __half g_ctx[(size_t)Mn * HIDn];            // ctx fp16 [B,S,H*D]

// ---------------------------------------------------------------------------
// helpers
// ---------------------------------------------------------------------------
__device__ __forceinline__ uint32_t smem_u32(const void* p) {
    uint32_t a;
    asm("{ .reg .u64 t; cvta.to.shared.u64 t, %1; cvt.u32.u64 %0, t; }"
        : "=r"(a) : "l"(p));
    return a;
}
__device__ __forceinline__ void cpasync16(uint32_t saddr, const void* g) {
    asm volatile("cp.async.cg.shared.global [%0], [%1], 16;" :: "r"(saddr), "l"(g));
}
__device__ __forceinline__ void mma_f16(float c[4], const uint32_t a[4], const uint32_t b[2]) {
    asm volatile("mma.sync.aligned.m16n8k16.row.col.f32.f16.f16.f32 "
                 "{%0,%1,%2,%3}, {%4,%5,%6,%7}, {%8,%9}, {%0,%1,%2,%3};"
                 : "+f"(c[0]), "+f"(c[1]), "+f"(c[2]), "+f"(c[3])
                 : "r"(a[0]), "r"(a[1]), "r"(a[2]), "r"(a[3]), "r"(b[0]), "r"(b[1]));
}
#define LDMX4(r, addr)                                                                  \
    asm volatile("ldmatrix.sync.aligned.m8n8.x4.shared.b16 {%0,%1,%2,%3}, [%4];"        \
                 : "=r"((r)[0]), "=r"((r)[1]), "=r"((r)[2]), "=r"((r)[3]) : "r"(addr))
#define LDMX4T(r, addr)                                                                 \
    asm volatile("ldmatrix.sync.aligned.m8n8.x4.trans.shared.b16 {%0,%1,%2,%3}, [%4];"  \
                 : "=r"((r)[0]), "=r"((r)[1]), "=r"((r)[2]), "=r"((r)[3]) : "r"(addr))

// ---------------------------------------------------------------------------
// fp32 -> fp16 conversion prepass
// ---------------------------------------------------------------------------
__global__ void __launch_bounds__(256) f2h(const float4* __restrict__ in,
                                           uint2* __restrict__ out, int n4) {
    int i = blockIdx.x * blockDim.x + threadIdx.x;
    if (i < n4) {
        float4 v = in[i];
        __half2 a = __floats2half2_rn(v.x, v.y);
        __half2 b = __floats2half2_rn(v.z, v.w);
        uint2 r;
        r.x = *reinterpret_cast<uint32_t*>(&a);
        r.y = *reinterpret_cast<uint32_t*>(&b);
        out[i] = r;
    }
}

// ---------------------------------------------------------------------------
// fp16 mma.sync NT-GEMM (unchanged from R7, proven)
// ---------------------------------------------------------------------------
#define LDW 40
#define TILE_H (128 * LDW)
#define STAGE_H (2 * TILE_H)
#define NSTG 3
#define GEMM_SMEM (NSTG * STAGE_H * 2)

template<int MODE>
__global__ void __launch_bounds__(256, 2) gemm_mma(const __half* __restrict__ A_,
                                                   const __half* __restrict__ W0,
                                                   const __half* __restrict__ W1,
                                                   const __half* __restrict__ W2,
                                                   float* __restrict__ fout,
                                                   __half* __restrict__ hq,
                                                   __half* __restrict__ hk,
                                                   __half* __restrict__ hv)
{
    extern __shared__ __half smh[];

    const int tid  = threadIdx.x;
    const int wid  = tid >> 5;
    const int lane = tid & 31;
    const int wm = (wid >> 2) * 64;
    const int wn = (wid & 3) * 32;

    const int m0 = blockIdx.y * 128;
    const int n0 = blockIdx.x * 128;
    int z = 0;
    const __half* W = W0;
    if (MODE == 0) { z = blockIdx.z; W = (z == 0) ? W0 : (z == 1) ? W1 : W2; }

    const int mat = lane >> 3;
    const int a_r = (mat & 1) * 8 + (lane & 7);
    const int a_c = (mat >> 1) * 8;
    const int bx_r = (lane >> 4) * 8 + (lane & 7);
    const int bx_c = ((lane >> 3) & 1) * 8;

    float acc[4][4][4] = {};

    auto load_stage = [&](int j) {
        __half* As = smh + (j % NSTG) * STAGE_H;
        __half* Bs = As + TILE_H;
        const int k0 = j * 32;
        #pragma unroll
        for (int i = 0; i < 2; i++) {
            int idx = tid + i * 256;
            int row = idx >> 2;
            int c   = idx & 3;
            cpasync16(smem_u32(As + row * LDW + c * 8),
                      A_ + (size_t)(m0 + row) * HIDn + k0 + c * 8);
            cpasync16(smem_u32(Bs + row * LDW + c * 8),
                      W  + (size_t)(n0 + row) * HIDn + k0 + c * 8);
        }
        asm volatile("cp.async.commit_group;");
    };

    const int nk = HIDn / 32;
    load_stage(0);
    load_stage(1);

    for (int j = 0; j < nk; j++) {
        if (j < nk - 2) {
            asm volatile("cp.async.wait_group 1;" ::: "memory");
        } else {
            asm volatile("cp.async.wait_group 0;" ::: "memory");
        }
        __syncthreads();
        if (j + 2 < nk) load_stage(j + 2);

        const __half* As = smh + (j % NSTG) * STAGE_H;
        const __half* Bs = As + TILE_H;

        #pragma unroll
        for (int ks = 0; ks < 2; ks++) {
            const int k0 = ks * 16;
            uint32_t a[4][4];
            #pragma unroll
            for (int i = 0; i < 4; i++)
                LDMX4(a[i], smem_u32(As + (wm + i * 16 + a_r) * LDW + k0 + a_c));
            uint32_t b4[2][4];
            #pragma unroll
            for (int tp = 0; tp < 2; tp++)
                LDMX4(b4[tp], smem_u32(Bs + (wn + tp * 16 + bx_r) * LDW + k0 + bx_c));
            #pragma unroll
            for (int i = 0; i < 4; i++)
                #pragma unroll
                for (int t = 0; t < 4; t++)
                    mma_f16(acc[i][t], a[i], &b4[t >> 1][(t & 1) * 2]);
        }
    }

    const int er = lane >> 2;
    const int ec = (lane & 3) * 2;

    #pragma unroll
    for (int i = 0; i < 4; i++) {
        const int r0 = m0 + wm + i * 16 + er;
        #pragma unroll
        for (int half = 0; half < 2; half++) {
            const int m = r0 + half * 8;
            if (MODE == 1) {
                size_t o = (size_t)m * HIDn + n0 + wn + ec;
                #pragma unroll
                for (int t = 0; t < 4; t++) {
                    float2 v = make_float2(acc[i][t][half * 2], acc[i][t][half * 2 + 1]);
                    *reinterpret_cast<float2*>(fout + o + t * 8) = v;
                }
            } else {
                const int b = m >> 11;
                const int s = m & (Sn - 1);
                const int h = n0 >> 7;
                const int d0 = wn + ec;
                size_t hb = (((size_t)(b * Hn + h)) * Sn + s) * Dn + d0;
                if (z == 0) {
                    #pragma unroll
                    for (int t = 0; t < 4; t++) {
                        __half2 hv2 = __floats2half2_rn(acc[i][t][half * 2], acc[i][t][half * 2 + 1]);
                        *reinterpret_cast<__half2*>(hq + hb + t * 8) = hv2;
                    }
                } else {
                    size_t fb = ((((size_t)(b * Hn + h)) * 2 + (z - 1)) * Sn + s) * Dn + d0;
                    __half* hm = (z == 1) ? hk : hv;
                    #pragma unroll
                    for (int t = 0; t < 4; t++) {
                        float2 v = make_float2(acc[i][t][half * 2], acc[i][t][half * 2 + 1]);
                        *reinterpret_cast<float2*>(fout + fb + t * 8) = v;
                        __half2 hv2 = __floats2half2_rn(v.x, v.y);
                        *reinterpret_cast<__half2*>(hm + hb + t * 8) = hv2;
                    }
                }
            }
        }
    }
}

// ---------------------------------------------------------------------------
// fp16 tensor-core causal flash attention, cp.async double-buffered K/V.
// CTA: 128 q-rows, 256 threads = 8 warps x 16 rows. 64-key tiles.
// Pipeline: wait(tile j) -> sync -> issue loads(tile j+1) -> compute(tile j).
// ---------------------------------------------------------------------------
#define LDQ 136
#define LDK 136
#define LDP 72
#define KVBUF_H (64 * LDK)                       // one K or V tile, halves
#define OFF_KV  0                                // 2 stages x (K+V): 4*KVBUF_H
#define OFF_PS  (4 * KVBUF_H)                    // 34816
#define OFF_QS  (OFF_PS + 128 * LDP)             // 44032
#define ATT_SMEM_H (OFF_QS + 128 * LDQ)          // 61440 halves
#define ATT_SMEM_B (ATT_SMEM_H * 2)              // 122880 bytes

__global__ void __launch_bounds__(256, 1) attn_mma(const __half* __restrict__ q,
                                                   const __half* __restrict__ kh,
                                                   const __half* __restrict__ vh,
                                                   __half* __restrict__ ctx)
{
    extern __shared__ __half smh[];
    __half* Psh = smh + OFF_PS;   // [128][LDP]
    __half* Qs  = smh + OFF_QS;   // [128][LDQ]

    const int q0 = blockIdx.x * 128;
    const int bh = blockIdx.y;
    const __half* qb = q  + (size_t)bh * Sn * Dn;
    const __half* kb = kh + (size_t)bh * Sn * Dn;
    const __half* vb = vh + (size_t)bh * Sn * Dn;

    const int tid  = threadIdx.x;
    const int wid  = tid >> 5;
    const int lane = tid & 31;
    const int w16  = wid * 16;

    const int mat = lane >> 3;
    const int a_r = (mat & 1) * 8 + (lane & 7);
    const int a_c = (mat >> 1) * 8;
    const int b_r = (lane >> 4) * 8 + (lane & 7);        // B no-trans
    const int b_c = ((lane >> 3) & 1) * 8;
    const int v_r = ((lane >> 3) & 1) * 8 + (lane & 7);  // V trans
    const int v_c = (lane >> 4) * 8;

    // per-tile K/V loader (cp.async, one commit group per tile)
    auto load_kv = [&](int jt) {
        __half* Kb = smh + OFF_KV + (jt & 1) * 2 * KVBUF_H;
        __half* Vb = Kb + KVBUF_H;
        const int j0 = jt * 64;
        #pragma unroll
        for (int i = 0; i < 4; i++) {
            int idx = tid + i * 256;   // 0..1023
            int row = idx >> 4;        // 0..63
            int c   = idx & 15;
            cpasync16(smem_u32(Kb + row * LDK + c * 8),
                      kb + (size_t)(j0 + row) * Dn + c * 8);
            cpasync16(smem_u32(Vb + row * LDK + c * 8),
                      vb + (size_t)(j0 + row) * Dn + c * 8);
        }
        asm volatile("cp.async.commit_group;");
    };

    // ---- prologue: Q tile (cp.async) + prefetch tile 0 ----
    #pragma unroll
    for (int i = 0; i < 8; i++) {
        int idx = tid + i * 256;
        int row = idx >> 4;
        int c   = idx & 15;
        cpasync16(smem_u32(Qs + row * LDQ + c * 8),
                  qb + (size_t)(q0 + row) * Dn + c * 8);
    }
    asm volatile("cp.async.commit_group;");
    load_kv(0);
    asm volatile("cp.async.wait_group 0;" ::: "memory");
    __syncthreads();

    uint32_t qa[8][4];
    #pragma unroll
    for (int ks = 0; ks < 8; ks++)
        LDMX4(qa[ks], smem_u32(Qs + (w16 + a_r) * LDQ + ks * 16 + a_c));

    float acc[16][4] = {};
    float m0r = -1e30f, m1r = -1e30f, l0r = 0.0f, l1r = 0.0f;
    const float scale = 0.08838834764831845f;
    const int r0 = lane >> 2;
    const int pc = (lane & 3) * 2;
    const int qg0 = q0 + w16 + r0;
    const int qg1 = qg0 + 8;
    const int nkt = (q0 >> 6) + 2;

    for (int jt = 0; jt < nkt; jt++) {
        const int j0 = jt * 64;

        if (jt > 0) {
            asm volatile("cp.async.wait_group 0;" ::: "memory");  // tile jt landed
            __syncthreads();                                      // all warps done with jt-1
        }
        if (jt + 1 < nkt) load_kv(jt + 1);   // overlaps compute of tile jt

        const __half* Ks = smh + OFF_KV + (jt & 1) * 2 * KVBUF_H;
        const __half* Vs = Ks + KVBUF_H;

        // ---- scores = Q K^T ----
        float sc[8][4] = {};
        #pragma unroll
        for (int ks = 0; ks < 8; ks++) {
            uint32_t kb4[4][4];
            #pragma unroll
            for (int tp = 0; tp < 4; tp++)
                LDMX4(kb4[tp], smem_u32(Ks + (tp * 16 + b_r) * LDK + ks * 16 + b_c));
            #pragma unroll
            for (int t = 0; t < 8; t++)
                mma_f16(sc[t], qa[ks], &kb4[t >> 1][(t & 1) * 2]);
        }

        // ---- scale + causal mask ----
        if (j0 + 63 > q0 + w16) {
            #pragma unroll
            for (int t = 0; t < 8; t++) {
                int c0 = j0 + t * 8 + pc;
                sc[t][0] = (c0     <= qg0) ? sc[t][0] * scale : -1e30f;
                sc[t][1] = (c0 + 1 <= qg0) ? sc[t][1] * scale : -1e30f;
                sc[t][2] = (c0     <= qg1) ? sc[t][2] * scale : -1e30f;
                sc[t][3] = (c0 + 1 <= qg1) ? sc[t][3] * scale : -1e30f;
            }
        } else {
            #pragma unroll
            for (int t = 0; t < 8; t++) {
                sc[t][0] *= scale; sc[t][1] *= scale;
                sc[t][2] *= scale; sc[t][3] *= scale;
            }
        }

        // ---- online softmax ----
        float mx0 = -1e30f, mx1 = -1e30f;
        #pragma unroll
        for (int t = 0; t < 8; t++) {
            mx0 = fmaxf(mx0, fmaxf(sc[t][0], sc[t][1]));
            mx1 = fmaxf(mx1, fmaxf(sc[t][2], sc[t][3]));
        }
        mx0 = fmaxf(mx0, __shfl_xor_sync(0xffffffffu, mx0, 1));
        mx0 = fmaxf(mx0, __shfl_xor_sync(0xffffffffu, mx0, 2));
        mx1 = fmaxf(mx1, __shfl_xor_sync(0xffffffffu, mx1, 1));
        mx1 = fmaxf(mx1, __shfl_xor_sync(0xffffffffu, mx1, 2));

        float nm0 = fmaxf(m0r, mx0), nm1 = fmaxf(m1r, mx1);
        float al0 = __expf(m0r - nm0), al1 = __expf(m1r - nm1);
        m0r = nm0; m1r = nm1;

        float s0 = 0.0f, s1 = 0.0f;
        #pragma unroll
        for (int t = 0; t < 8; t++) {
            sc[t][0] = __expf(sc[t][0] - nm0);
            sc[t][1] = __expf(sc[t][1] - nm0);
            sc[t][2] = __expf(sc[t][2] - nm1);
            sc[t][3] = __expf(sc[t][3] - nm1);
            s0 += sc[t][0] + sc[t][1];
            s1 += sc[t][2] + sc[t][3];
        }
        s0 += __shfl_xor_sync(0xffffffffu, s0, 1);
        s0 += __shfl_xor_sync(0xffffffffu, s0, 2);
        s1 += __shfl_xor_sync(0xffffffffu, s1, 1);
        s1 += __shfl_xor_sync(0xffffffffu, s1, 2);
        l0r = l0r * al0 + s0;
        l1r = l1r * al1 + s1;

        #pragma unroll
        for (int t = 0; t < 16; t++) {
            acc[t][0] *= al0; acc[t][1] *= al0;
            acc[t][2] *= al1; acc[t][3] *= al1;
        }

        // ---- stage P (fp16, own warp's rows) ----
        #pragma unroll
        for (int t = 0; t < 8; t++) {
            *reinterpret_cast<__half2*>(Psh + (w16 + r0)     * LDP + t * 8 + pc) =
                __floats2half2_rn(sc[t][0], sc[t][1]);
            *reinterpret_cast<__half2*>(Psh + (w16 + r0 + 8) * LDP + t * 8 + pc) =
                __floats2half2_rn(sc[t][2], sc[t][3]);
        }
        __syncwarp();

        // ---- acc += P V ----
        #pragma unroll
        for (int kp = 0; kp < 4; kp++) {
            uint32_t pa[4];
            LDMX4(pa, smem_u32(Psh + (w16 + a_r) * LDP + kp * 16 + a_c));
            #pragma unroll
            for (int dp = 0; dp < 8; dp++) {
                uint32_t vb4[4];
                LDMX4T(vb4, smem_u32(Vs + (kp * 16 + v_r) * LDK + dp * 16 + v_c));
                mma_f16(acc[dp * 2],     pa, &vb4[0]);
                mma_f16(acc[dp * 2 + 1], pa, &vb4[2]);
            }
        }
    }

    // ---- epilogue: ctx fp16 [b][s][h*128 + d] ----
    const int b = bh >> 4;
    const int h = bh & 15;
    const float inv0 = 1.0f / l0r;
    const float inv1 = 1.0f / l1r;
    size_t base0 = ((size_t)b * Sn + qg0) * (Hn * Dn) + h * Dn + pc;
    size_t base1 = ((size_t)b * Sn + qg1) * (Hn * Dn) + h * Dn + pc;
    #pragma unroll
    for (int t = 0; t < 16; t++) {
        *reinterpret_cast<__half2*>(ctx + base0 + t * 8) =
            __floats2half2_rn(acc[t][0] * inv0, acc[t][1] * inv0);
        *reinterpret_cast<__half2*>(ctx + base1 + t * 8) =
            __floats2half2_rn(acc[t][2] * inv1, acc[t][3] * inv1);
    }
}

// ---------------------------------------------------------------------------
// Launch
// ---------------------------------------------------------------------------
extern "C" void kernel_launch(void* const* d_in, const int* in_sizes, int n_in,
                              void* d_out, int out_size)
{
    const float* x  = (const float*)d_in[0];
    const float* Wq = (const float*)d_in[1];
    const float* Wk = (const float*)d_in[2];
    const float* Wv = (const float*)d_in[3];
    const float* Wo = (const float*)d_in[4];

    float* out = (float*)d_out;                    // [B,S,HID]
    float* kv  = out + (size_t)Bn * Sn * HIDn;     // [B,H,2,S,D]

    __half *xh, *wh, *qh, *kh, *vh, *ctxh;
    cudaGetSymbolAddress((void**)&xh,   g_xh);
    cudaGetSymbolAddress((void**)&wh,   g_wh);
    cudaGetSymbolAddress((void**)&qh,   g_qh);
    cudaGetSymbolAddress((void**)&kh,   g_kh);
    cudaGetSymbolAddress((void**)&vh,   g_vh);
    cudaGetSymbolAddress((void**)&ctxh, g_ctx);

    // 0) convert inputs to fp16
    {
        int n4x = Mn * HIDn / 4;
        int n4w = HIDn * HIDn / 4;
        f2h<<<(n4x + 255) / 256, 256>>>((const float4*)x,  (uint2*)xh, n4x);
        f2h<<<(n4w + 255) / 256, 256>>>((const float4*)Wq, (uint2*)(wh + 0 * (size_t)HIDn * HIDn), n4w);
        f2h<<<(n4w + 255) / 256, 256>>>((const float4*)Wk, (uint2*)(wh + 1 * (size_t)HIDn * HIDn), n4w);
        f2h<<<(n4w + 255) / 256, 256>>>((const float4*)Wv, (uint2*)(wh + 2 * (size_t)HIDn * HIDn), n4w);
        f2h<<<(n4w + 255) / 256, 256>>>((const float4*)Wo, (uint2*)(wh + 3 * (size_t)HIDn * HIDn), n4w);
    }

    // 1) Q/K/V projections (K,V fp32 straight into kv cache + fp16 mirrors)
    cudaFuncSetAttribute(gemm_mma<0>, cudaFuncAttributeMaxDynamicSharedMemorySize, GEMM_SMEM);
    cudaFuncSetAttribute(gemm_mma<1>, cudaFuncAttributeMaxDynamicSharedMemorySize, GEMM_SMEM);
    dim3 gproj(HIDn / 128, Mn / 128, 3);
    gemm_mma<0><<<gproj, 256, GEMM_SMEM>>>(xh,
                                           wh + 0 * (size_t)HIDn * HIDn,
                                           wh + 1 * (size_t)HIDn * HIDn,
                                           wh + 2 * (size_t)HIDn * HIDn,
                                           kv, qh, kh, vh);

    // 2) causal flash attention (fp16 tensor cores, pipelined K/V)
    cudaFuncSetAttribute(attn_mma, cudaFuncAttributeMaxDynamicSharedMemorySize, ATT_SMEM_B);
    dim3 gattn(Sn / 128, Bn * Hn);
    attn_mma<<<gattn, 256, ATT_SMEM_B>>>(qh, kh, vh, ctxh);

    // 3) output projection (fp32 result)
    dim3 gout(HIDn / 128, Mn / 128, 1);
    gemm_mma<1><<<gout, 256, GEMM_SMEM>>>(ctxh,
                                          wh + 3 * (size_t)HIDn * HIDn,
                                          nullptr, nullptr,
                                          out, nullptr, nullptr, nullptr);
}